// round 1
// baseline (speedup 1.0000x reference)
#include <cuda_runtime.h>
#include <cuda_bf16.h>
#include <math.h>
#include <stdint.h>
#include <stddef.h>

// Problem constants
#define NN_ 32768
#define EE_ 524288
#define CC_ 256
#define HH_ 8
#define BB_ 128
#define NCLS_ 10
#define PER_ 256
#define HD_ 32
#define EPS_ 1e-5f

// ---------------- scratch (static device globals; no allocation) ----------------
__device__ float g_h[NN_ * CC_];        // x @ W_conv
__device__ float g_h1[NN_ * CC_];       // gcn + x (pre-BN1)
__device__ float g_qkv[NN_ * 3 * CC_];  // qkv
__device__ float g_attn[NN_ * CC_];     // attention concat output
__device__ float g_h2[NN_ * CC_];       // out_proj + x (pre-BN2)
__device__ float g_out[NN_ * CC_];      // h1 + h2 (post-BN combine)
__device__ float g_ff1[NN_ * 2 * CC_];  // relu(out@w1+b1)
__device__ float g_out3[NN_ * CC_];     // out + ff (pre-BN3)
__device__ float g_deg[NN_];
__device__ float g_dinv[NN_];
__device__ float g_sum[3 * CC_];
__device__ float g_sq[3 * CC_];
__device__ float g_pooled[BB_ * CC_];

// ---------------- small helpers ----------------
__device__ __forceinline__ void red4(float* p, float x, float y, float z, float w) {
    asm volatile("red.global.add.v4.f32 [%0], {%1,%2,%3,%4};"
                 :: "l"(p), "f"(x), "f"(y), "f"(z), "f"(w) : "memory");
}

// init: deg=1 (self loops), zero BN stats
__global__ void init_kernel() {
    int i = blockIdx.x * blockDim.x + threadIdx.x;
    if (i < NN_) g_deg[i] = 1.0f;
    if (i < 3 * CC_) { g_sum[i] = 0.0f; g_sq[i] = 0.0f; }
}

__global__ void edge_deg_kernel(const int* __restrict__ col) {
    int e = blockIdx.x * blockDim.x + threadIdx.x;
    if (e < EE_) atomicAdd(&g_deg[col[e]], 1.0f);
}

__global__ void dinv_kernel() {
    int i = blockIdx.x * blockDim.x + threadIdx.x;
    if (i < NN_) g_dinv[i] = rsqrtf(g_deg[i]);
}

// g_h1 = dinv[n]^2 * h[n] + b_conv + x[n]   (self-loop term + bias + residual)
__global__ void agg_init_kernel(const float* __restrict__ x, const float* __restrict__ b_conv) {
    int idx = blockIdx.x * blockDim.x + threadIdx.x;
    if (idx >= NN_ * CC_) return;
    int n = idx >> 8, c = idx & 255;
    float di = g_dinv[n];
    g_h1[idx] = di * di * g_h[idx] + b_conv[c] + x[idx];
}

// one warp per edge: g_h1[col] += dinv[row]*dinv[col] * g_h[row]
__global__ void edge_agg_kernel(const int* __restrict__ row, const int* __restrict__ col) {
    int gt = blockIdx.x * blockDim.x + threadIdx.x;
    int e = gt >> 5;
    int lane = gt & 31;
    if (e >= EE_) return;
    int r = row[e], cl = col[e];
    float w = g_dinv[r] * g_dinv[cl];
    const float4* hp = (const float4*)(g_h + (size_t)r * CC_) + lane * 2;
    float4 a = hp[0], b = hp[1];
    float* dst = g_h1 + (size_t)cl * CC_ + lane * 8;
    red4(dst,     w * a.x, w * a.y, w * a.z, w * a.w);
    red4(dst + 4, w * b.x, w * b.y, w * b.z, w * b.w);
}

// per-channel sum/sumsq over rows; block handles 128 rows; thread = channel
__global__ void stats_kernel(const float* __restrict__ X, float* __restrict__ sum, float* __restrict__ sq) {
    int c = threadIdx.x;
    int r0 = blockIdx.x * 128;
    float s = 0.0f, q = 0.0f;
    #pragma unroll 4
    for (int r = 0; r < 128; r++) {
        float v = X[(size_t)(r0 + r) * CC_ + c];
        s += v; q += v * v;
    }
    atomicAdd(&sum[c], s);
    atomicAdd(&sq[c], q);
}

// ---------------- fp32 SGEMM: 128x128 tile, 8x8 microtile, 256 threads ----------------
// TB: B stored (Nn x K) row-major (use B^T). EPI: 0 none, 1 +bias, 2 +bias+relu, 3 +bias+resid
template<int TB, int EPI>
__global__ void gemm128(const float* __restrict__ A, const float* __restrict__ Bm,
                        const float* __restrict__ bias, const float* __restrict__ resid,
                        float* __restrict__ Cout, int M, int Nn, int K) {
    __shared__ float As[8][128];
    __shared__ float Bs[8][128];
    int tid = threadIdx.x;
    int tx = tid & 15, ty = tid >> 4;
    int row0 = blockIdx.y * 128, col0 = blockIdx.x * 128;
    float acc[8][8];
    #pragma unroll
    for (int i = 0; i < 8; i++)
        #pragma unroll
        for (int j = 0; j < 8; j++) acc[i][j] = 0.0f;

    int arow = tid >> 1;
    int akq = (tid & 1) * 4;
    int bkk = tid >> 5;
    int bn4 = (tid & 31) * 4;

    for (int k0 = 0; k0 < K; k0 += 8) {
        float4 av = *(const float4*)(A + (size_t)(row0 + arow) * K + k0 + akq);
        As[akq + 0][arow] = av.x; As[akq + 1][arow] = av.y;
        As[akq + 2][arow] = av.z; As[akq + 3][arow] = av.w;
        if (TB) {
            float4 bv = *(const float4*)(Bm + (size_t)(col0 + arow) * K + k0 + akq);
            Bs[akq + 0][arow] = bv.x; Bs[akq + 1][arow] = bv.y;
            Bs[akq + 2][arow] = bv.z; Bs[akq + 3][arow] = bv.w;
        } else {
            float4 bv = *(const float4*)(Bm + (size_t)(k0 + bkk) * Nn + col0 + bn4);
            *(float4*)&Bs[bkk][bn4] = bv;
        }
        __syncthreads();
        #pragma unroll
        for (int kk = 0; kk < 8; kk++) {
            float a[8], b[8];
            #pragma unroll
            for (int i = 0; i < 8; i++) a[i] = As[kk][ty * 8 + i];
            #pragma unroll
            for (int j = 0; j < 8; j++) b[j] = Bs[kk][tx * 8 + j];
            #pragma unroll
            for (int i = 0; i < 8; i++)
                #pragma unroll
                for (int j = 0; j < 8; j++) acc[i][j] += a[i] * b[j];
        }
        __syncthreads();
    }

    #pragma unroll
    for (int i = 0; i < 8; i++) {
        int r = row0 + ty * 8 + i;
        #pragma unroll
        for (int j = 0; j < 8; j++) {
            int cc = col0 + tx * 8 + j;
            float v = acc[i][j];
            if (EPI >= 1) v += bias[cc];
            if (EPI == 2) v = fmaxf(v, 0.0f);
            if (EPI == 3) v += resid[(size_t)r * Nn + cc];
            Cout[(size_t)r * Nn + cc] = v;
        }
    }
}

// ---------------- attention: one block per (graph, head); online softmax ----------------
__global__ void attn_kernel(const float* __restrict__ qkv, float* __restrict__ out) {
    extern __shared__ float smem[];
    float* ks = smem;              // [PER_*HD_]
    float* vs = smem + PER_ * HD_; // [PER_*HD_]
    int bx = blockIdx.x;
    int b = bx >> 3, h = bx & 7;
    int base = b * PER_;
    int tid = threadIdx.x;

    // cooperative load of K, V slices for this (b, h)
    for (int i = tid; i < PER_ * HD_; i += 256) {
        int j = i >> 5, d = i & 31;
        size_t rowoff = (size_t)(base + j) * (3 * CC_) + h * HD_;
        ks[i] = qkv[rowoff + CC_ + d];
        vs[i] = qkv[rowoff + 2 * CC_ + d];
    }
    __syncthreads();

    // each thread handles one query
    int p = tid;
    float q[HD_];
    const float* qp = qkv + (size_t)(base + p) * (3 * CC_) + h * HD_;
    #pragma unroll
    for (int d = 0; d < HD_; d++) q[d] = qp[d];

    float m = -INFINITY, l = 0.0f;
    float o[HD_];
    #pragma unroll
    for (int d = 0; d < HD_; d++) o[d] = 0.0f;

    const float scale = 0.17677669529663687f; // 1/sqrt(32)
    for (int j = 0; j < PER_; j++) {
        float s = 0.0f;
        const float* kj = ks + j * HD_;
        #pragma unroll
        for (int d = 0; d < HD_; d++) s += q[d] * kj[d];
        s *= scale;
        float mn = fmaxf(m, s);
        float corr = __expf(m - mn);   // first iter: exp(-inf)=0, o is 0 anyway
        float pw = __expf(s - mn);
        l = l * corr + pw;
        const float* vj = vs + j * HD_;
        #pragma unroll
        for (int d = 0; d < HD_; d++) o[d] = o[d] * corr + pw * vj[d];
        m = mn;
    }
    float inv = 1.0f / l;
    float* op = out + (size_t)(base + p) * CC_ + h * HD_;
    #pragma unroll
    for (int d = 0; d < HD_; d++) op[d] = o[d] * inv;
}

// ---------------- combine: out = BN1(h1) + BN2(h2) ----------------
__global__ void combine_kernel(const float* __restrict__ g1, const float* __restrict__ b1,
                               const float* __restrict__ g2, const float* __restrict__ b2) {
    int idx = blockIdx.x * blockDim.x + threadIdx.x;
    if (idx >= NN_ * CC_) return;
    int c = idx & 255;
    const float invN = 1.0f / (float)NN_;
    float m1 = g_sum[c] * invN;
    float v1 = g_sq[c] * invN - m1 * m1;
    float s1 = g1[c] * rsqrtf(v1 + EPS_);
    float m2 = g_sum[CC_ + c] * invN;
    float v2 = g_sq[CC_ + c] * invN - m2 * m2;
    float s2 = g2[c] * rsqrtf(v2 + EPS_);
    float y1 = (g_h1[idx] - m1) * s1 + b1[c];
    float y2 = (g_h2[idx] - m2) * s2 + b2[c];
    g_out[idx] = y1 + y2;
}

// ---------------- pool: per-graph max of BN3(out3) ----------------
__global__ void pool_kernel(const float* __restrict__ g3, const float* __restrict__ b3) {
    int g = blockIdx.x;
    int c = threadIdx.x;
    const float invN = 1.0f / (float)NN_;
    float m3 = g_sum[2 * CC_ + c] * invN;
    float v3 = g_sq[2 * CC_ + c] * invN - m3 * m3;
    float s3 = g3[c] * rsqrtf(v3 + EPS_);
    float sh = b3[c] - m3 * s3;
    float mx = -INFINITY;
    for (int p = 0; p < PER_; p++) {
        float v = g_out3[(size_t)(g * PER_ + p) * CC_ + c];
        mx = fmaxf(mx, v * s3 + sh);
    }
    g_pooled[g * CC_ + c] = mx;
}

// ---------------- head: logits + log_softmax ----------------
__global__ void head_kernel(const float* __restrict__ fc_w, const float* __restrict__ fc_b,
                            float* __restrict__ out) {
    int g = blockIdx.x;
    int tid = threadIdx.x;
    __shared__ float pr[CC_];
    __shared__ float lo[NCLS_];
    __shared__ float red[2];
    pr[tid] = g_pooled[g * CC_ + tid];
    __syncthreads();
    if (tid < NCLS_) {
        float s = fc_b[tid];
        for (int c = 0; c < CC_; c++) s += pr[c] * fc_w[c * NCLS_ + tid];
        lo[tid] = s;
    }
    __syncthreads();
    if (tid == 0) {
        float mx = -INFINITY;
        for (int j = 0; j < NCLS_; j++) mx = fmaxf(mx, lo[j]);
        float se = 0.0f;
        for (int j = 0; j < NCLS_; j++) se += __expf(lo[j] - mx);
        red[0] = mx;
        red[1] = logf(se);
    }
    __syncthreads();
    if (tid < NCLS_) out[g * NCLS_ + tid] = lo[tid] - red[0] - red[1];
}

// ---------------- launch ----------------
extern "C" void kernel_launch(void* const* d_in, const int* in_sizes, int n_in,
                              void* d_out, int out_size) {
    const float* x          = (const float*)d_in[0];
    const float* W_conv     = (const float*)d_in[1];
    const float* b_conv     = (const float*)d_in[2];
    const float* bn1_g      = (const float*)d_in[3];
    const float* bn1_b      = (const float*)d_in[4];
    const float* in_proj_w  = (const float*)d_in[5];
    const float* in_proj_b  = (const float*)d_in[6];
    const float* out_proj_w = (const float*)d_in[7];
    const float* out_proj_b = (const float*)d_in[8];
    const float* bn2_g      = (const float*)d_in[9];
    const float* bn2_b      = (const float*)d_in[10];
    const float* mlp_w1     = (const float*)d_in[11];
    const float* mlp_b1     = (const float*)d_in[12];
    const float* mlp_w2     = (const float*)d_in[13];
    const float* mlp_b2     = (const float*)d_in[14];
    const float* bn3_g      = (const float*)d_in[15];
    const float* bn3_b      = (const float*)d_in[16];
    const float* fc_w       = (const float*)d_in[17];
    const float* fc_b       = (const float*)d_in[18];
    const int*   edge_index = (const int*)d_in[19];
    // d_in[20] = batch (structure exploited: node n -> graph n/PER_)
    float* out = (float*)d_out;

    const int* row = edge_index;
    const int* col = edge_index + EE_;

    // raise dynamic smem limit for attention (64 KB); not a stream op, capture-safe
    cudaFuncSetAttribute(attn_kernel, cudaFuncAttributeMaxDynamicSharedMemorySize,
                         2 * PER_ * HD_ * (int)sizeof(float));

    init_kernel<<<NN_ / 256, 256>>>();
    edge_deg_kernel<<<EE_ / 256, 256>>>(col);
    dinv_kernel<<<NN_ / 256, 256>>>();

    // GCN: h = x @ W_conv
    {
        float* g_h_p; cudaGetSymbolAddress((void**)&g_h_p, g_h);
        float* g_h1_p; cudaGetSymbolAddress((void**)&g_h1_p, g_h1);
        gemm128<0, 0><<<dim3(CC_ / 128, NN_ / 128), 256>>>(x, W_conv, nullptr, nullptr, g_h_p, NN_, CC_, CC_);
        agg_init_kernel<<<NN_ * CC_ / 256, 256>>>(x, b_conv);
        edge_agg_kernel<<<EE_ * 32 / 256, 256>>>(row, col);
        float* sum_p; cudaGetSymbolAddress((void**)&sum_p, g_sum);
        float* sq_p;  cudaGetSymbolAddress((void**)&sq_p,  g_sq);
        stats_kernel<<<NN_ / 128, 256>>>(g_h1_p, sum_p, sq_p);

        // attention branch
        float* qkv_p;  cudaGetSymbolAddress((void**)&qkv_p,  g_qkv);
        float* attn_p; cudaGetSymbolAddress((void**)&attn_p, g_attn);
        float* h2_p;   cudaGetSymbolAddress((void**)&h2_p,   g_h2);
        gemm128<1, 1><<<dim3(3 * CC_ / 128, NN_ / 128), 256>>>(x, in_proj_w, in_proj_b, nullptr, qkv_p, NN_, 3 * CC_, CC_);
        attn_kernel<<<BB_ * HH_, 256, 2 * PER_ * HD_ * (int)sizeof(float)>>>(qkv_p, attn_p);
        gemm128<1, 3><<<dim3(CC_ / 128, NN_ / 128), 256>>>(attn_p, out_proj_w, out_proj_b, x, h2_p, NN_, CC_, CC_);
        stats_kernel<<<NN_ / 128, 256>>>(h2_p, sum_p + CC_, sq_p + CC_);

        // combine + FFN
        float* out_p;  cudaGetSymbolAddress((void**)&out_p,  g_out);
        float* ff1_p;  cudaGetSymbolAddress((void**)&ff1_p,  g_ff1);
        float* out3_p; cudaGetSymbolAddress((void**)&out3_p, g_out3);
        combine_kernel<<<NN_ * CC_ / 256, 256>>>(bn1_g, bn1_b, bn2_g, bn2_b);
        gemm128<0, 2><<<dim3(2 * CC_ / 128, NN_ / 128), 256>>>(out_p, mlp_w1, mlp_b1, nullptr, ff1_p, NN_, 2 * CC_, CC_);
        gemm128<0, 3><<<dim3(CC_ / 128, NN_ / 128), 256>>>(ff1_p, mlp_w2, mlp_b2, out_p, out3_p, NN_, CC_, 2 * CC_);
        stats_kernel<<<NN_ / 128, 256>>>(out3_p, sum_p + 2 * CC_, sq_p + 2 * CC_);

        // pool + classifier head
        pool_kernel<<<BB_, CC_>>>(bn3_g, bn3_b);
        head_kernel<<<BB_, CC_>>>(fc_w, fc_b, out);
    }
}

// round 3
// speedup vs baseline: 1.8333x; 1.8333x over previous
#include <cuda_runtime.h>
#include <cuda_bf16.h>
#include <math.h>
#include <stdint.h>
#include <stddef.h>

// Problem constants
#define NN_ 32768
#define EE_ 524288
#define CC_ 256
#define HH_ 8
#define BB_ 128
#define NCLS_ 10
#define PER_ 256
#define HD_ 32
#define EPS_ 1e-5f

// ---------------- scratch (static device globals; no allocation) ----------------
__device__ float g_h[NN_ * CC_];        // x @ W_conv
__device__ float g_h1[NN_ * CC_];       // gcn + x (pre-BN1)
__device__ float g_qkv[NN_ * 3 * CC_];  // qkv
__device__ float g_attn[NN_ * CC_];     // attention concat output
__device__ float g_h2[NN_ * CC_];       // out_proj + x (pre-BN2)
__device__ float g_out[NN_ * CC_];      // h1 + h2 (post-BN combine)
__device__ float g_ff1[NN_ * 2 * CC_];  // relu(out@w1+b1)
__device__ float g_out3[NN_ * CC_];     // out + ff (pre-BN3)
__device__ float g_deg[NN_];
__device__ float g_dinv[NN_];
__device__ float g_sum[3 * CC_];
__device__ float g_sq[3 * CC_];
__device__ float g_pooled[BB_ * CC_];
// transposed weights (N x K, K-major) for the mma B operand
__device__ float g_WcT[CC_ * CC_];
__device__ float g_W1T[2 * CC_ * CC_];
__device__ float g_W2T[CC_ * 2 * CC_];

// ---------------- helpers ----------------
__device__ __forceinline__ uint32_t smem_u32(const void* p) {
    uint32_t a;
    asm("{ .reg .u64 t; cvta.to.shared.u64 t, %1; cvt.u32.u64 %0, t; }" : "=r"(a) : "l"(p));
    return a;
}
#define CP_COMMIT() asm volatile("cp.async.commit_group;" ::: "memory")
#define CP_WAIT1() asm volatile("cp.async.wait_group 1;" ::: "memory")
#define CP_WAIT0() asm volatile("cp.async.wait_group 0;" ::: "memory")

__device__ __forceinline__ uint32_t f2tf(float x) {
    uint32_t u;
    asm("cvt.rna.tf32.f32 %0, %1;" : "=r"(u) : "f"(x));
    return u;
}

// m16n8k8 tf32 MMA (sm_80+ PTX, assembles on plain compute_100)
__device__ __forceinline__ void mma8(float* c, const uint32_t* a, const uint32_t* b) {
    asm volatile("mma.sync.aligned.m16n8k8.row.col.f32.tf32.tf32.f32 "
        "{%0,%1,%2,%3}, {%4,%5,%6,%7}, {%8,%9}, {%0,%1,%2,%3};"
        : "+f"(c[0]), "+f"(c[1]), "+f"(c[2]), "+f"(c[3])
        : "r"(a[0]), "r"(a[1]), "r"(a[2]), "r"(a[3]), "r"(b[0]), "r"(b[1]));
}

__device__ __forceinline__ void red4(float* p, float x, float y, float z, float w) {
    asm volatile("red.global.add.v4.f32 [%0], {%1,%2,%3,%4};"
                 :: "l"(p), "f"(x), "f"(y), "f"(z), "f"(w) : "memory");
}

// fast exp on the FMA pipe (no MUFU): exp(x) = 2^(x*log2e)
__device__ __forceinline__ float fast_exp(float x) {
    float z = x * 1.4426950408889634f;
    float fz = z + 12582912.0f;                 // round-to-nearest into mantissa
    int n = __float_as_int(fz) - 0x4B400000;    // round(z)
    float f = z - (fz - 12582912.0f);           // frac in [-0.5, 0.5]
    float p = 0.0013333558f;
    p = fmaf(p, f, 0.0096181291f);
    p = fmaf(p, f, 0.0555041087f);
    p = fmaf(p, f, 0.2402265070f);
    p = fmaf(p, f, 0.6931471806f);
    p = fmaf(p, f, 1.0f);
    return p * __int_as_float((n + 127) << 23);
}

// ---------------- small kernels ----------------
__global__ void init_kernel() {
    int i = blockIdx.x * blockDim.x + threadIdx.x;
    if (i < NN_) g_deg[i] = 1.0f;
    if (i < 3 * CC_) { g_sum[i] = 0.0f; g_sq[i] = 0.0f; }
}

__global__ void edge_deg_kernel(const int* __restrict__ col) {
    int e = blockIdx.x * blockDim.x + threadIdx.x;
    if (e < EE_) atomicAdd(&g_deg[col[e]], 1.0f);
}

__global__ void dinv_kernel() {
    int i = blockIdx.x * blockDim.x + threadIdx.x;
    if (i < NN_) g_dinv[i] = rsqrtf(g_deg[i]);
}

__global__ void agg_init_kernel(const float* __restrict__ x, const float* __restrict__ b_conv) {
    int idx = blockIdx.x * blockDim.x + threadIdx.x;
    if (idx >= NN_ * CC_) return;
    int n = idx >> 8, c = idx & 255;
    float di = g_dinv[n];
    g_h1[idx] = di * di * g_h[idx] + b_conv[c] + x[idx];
}

__global__ void edge_agg_kernel(const int* __restrict__ row, const int* __restrict__ col) {
    int gt = blockIdx.x * blockDim.x + threadIdx.x;
    int e = gt >> 5;
    int lane = gt & 31;
    if (e >= EE_) return;
    int r = row[e], cl = col[e];
    float w = g_dinv[r] * g_dinv[cl];
    const float4* hp = (const float4*)(g_h + (size_t)r * CC_) + lane * 2;
    float4 a = hp[0], b = hp[1];
    float* dst = g_h1 + (size_t)cl * CC_ + lane * 8;
    red4(dst,     w * a.x, w * a.y, w * a.z, w * a.w);
    red4(dst + 4, w * b.x, w * b.y, w * b.z, w * b.w);
}

__global__ void stats_kernel(const float* __restrict__ X, float* __restrict__ sum, float* __restrict__ sq) {
    int c = threadIdx.x;
    int r0 = blockIdx.x * 128;
    float s = 0.0f, q = 0.0f;
    #pragma unroll 4
    for (int r = 0; r < 128; r++) {
        float v = X[(size_t)(r0 + r) * CC_ + c];
        s += v; q += v * v;
    }
    atomicAdd(&sum[c], s);
    atomicAdd(&sq[c], q);
}

// transpose in[R][Cc] -> out[Cc][R]
__global__ void transpose_kernel(const float* __restrict__ in, float* __restrict__ out, int R, int Cc) {
    __shared__ float t[32][33];
    int bx = blockIdx.x * 32, by = blockIdx.y * 32;
    int x = bx + threadIdx.x;
    #pragma unroll
    for (int i = 0; i < 32; i += 8) t[threadIdx.y + i][threadIdx.x] = in[(size_t)(by + threadIdx.y + i) * Cc + x];
    __syncthreads();
    int xo = by + threadIdx.x;
    #pragma unroll
    for (int i = 0; i < 32; i += 8) out[(size_t)(bx + threadIdx.y + i) * R + xo] = t[threadIdx.x][threadIdx.y + i];
}

// ---------------- tf32 mma.sync GEMM: 128x128 tile, 8 warps, cp.async double buffer ----
// A [M x K] row-major, Bt [Nn x K] row-major. EPI: 0 none, 1 bias, 2 bias+relu, 3 bias+resid
// smem chunk: 128 rows x 16 k-floats, padded row stride 20 floats (80 B, 16B-aligned,
// bank pattern (r*20+c) mod 32 is conflict-free for the fragment access patterns).
#define KCH 16
#define RST 20
#define CHUNK_FLOATS (128 * RST)          // 2560 floats = 10240 B per matrix
#define BUF_FLOATS (2 * CHUNK_FLOATS)     // A + B per stage
#define GEMM_SMEM (2 * BUF_FLOATS * 4)    // 40960 B

__device__ __forceinline__ void ld_chunk(uint32_t dst, const float* __restrict__ g,
                                         int ld, int row0, int k0, int tid) {
    #pragma unroll
    for (int i = 0; i < 2; i++) {
        int seg = i * 256 + tid;          // 512 segments of 16 B
        int r = seg >> 2, s = seg & 3;
        uint32_t d = dst + (uint32_t)(r * (RST * 4) + s * 16);
        const float* src = g + (size_t)(row0 + r) * ld + k0 + s * 4;
        asm volatile("cp.async.cg.shared.global [%0], [%1], 16;" :: "r"(d), "l"(src));
    }
}

template<int EPI>
__global__ void __launch_bounds__(256, 2) gemm_mma(
    const float* __restrict__ A, const float* __restrict__ Bt,
    const float* __restrict__ bias, const float* __restrict__ resid,
    float* __restrict__ C, int Nn, int K)
{
    extern __shared__ float smf[];
    uint32_t sb = smem_u32(smf);
    int tid = threadIdx.x;
    int wid = tid >> 5, lane = tid & 31;
    int grp = lane >> 2, qd = lane & 3;
    int wm = wid >> 1, wn = wid & 1;          // warp grid 4 (m) x 2 (n)
    int row0 = blockIdx.y * 128, col0 = blockIdx.x * 128;

    float acc[2][8][4];
    #pragma unroll
    for (int mf = 0; mf < 2; mf++)
        #pragma unroll
        for (int nf = 0; nf < 8; nf++)
            #pragma unroll
            for (int j = 0; j < 4; j++) acc[mf][nf][j] = 0.0f;

    int nch = K >> 4;
    ld_chunk(sb, A, K, row0, 0, tid);
    ld_chunk(sb + CHUNK_FLOATS * 4, Bt, K, col0, 0, tid);
    CP_COMMIT();

    for (int c = 0; c < nch; c++) {
        int s = c & 1;
        if (c + 1 < nch) {
            int s2 = s ^ 1;
            ld_chunk(sb + s2 * BUF_FLOATS * 4, A, K, row0, (c + 1) << 4, tid);
            ld_chunk(sb + s2 * BUF_FLOATS * 4 + CHUNK_FLOATS * 4, Bt, K, col0, (c + 1) << 4, tid);
            CP_COMMIT();
            CP_WAIT1();
        } else {
            CP_WAIT0();
        }
        __syncthreads();
        const float* As = smf + s * BUF_FLOATS;
        const float* Bs = smf + s * BUF_FLOATS + CHUNK_FLOATS;
        #pragma unroll
        for (int k8 = 0; k8 < KCH; k8 += 8) {
            uint32_t a[2][4], b[8][2];
            #pragma unroll
            for (int mf = 0; mf < 2; mf++) {
                int r = wm * 32 + mf * 16 + grp;
                a[mf][0] = f2tf(As[r * RST + k8 + qd]);
                a[mf][1] = f2tf(As[(r + 8) * RST + k8 + qd]);
                a[mf][2] = f2tf(As[r * RST + k8 + qd + 4]);
                a[mf][3] = f2tf(As[(r + 8) * RST + k8 + qd + 4]);
            }
            #pragma unroll
            for (int nf = 0; nf < 8; nf++) {
                int n = wn * 64 + nf * 8 + grp;
                b[nf][0] = f2tf(Bs[n * RST + k8 + qd]);
                b[nf][1] = f2tf(Bs[n * RST + k8 + qd + 4]);
            }
            #pragma unroll
            for (int mf = 0; mf < 2; mf++)
                #pragma unroll
                for (int nf = 0; nf < 8; nf++)
                    mma8(acc[mf][nf], a[mf], b[nf]);
        }
        __syncthreads();
    }

    // epilogue
    #pragma unroll
    for (int mf = 0; mf < 2; mf++) {
        int r1 = row0 + wm * 32 + mf * 16 + grp;
        #pragma unroll
        for (int nf = 0; nf < 8; nf++) {
            int cc = col0 + wn * 64 + nf * 8 + qd * 2;
            float2 v0 = make_float2(acc[mf][nf][0], acc[mf][nf][1]);
            float2 v1 = make_float2(acc[mf][nf][2], acc[mf][nf][3]);
            if (EPI >= 1) {
                float b0 = bias[cc], b1 = bias[cc + 1];
                v0.x += b0; v0.y += b1; v1.x += b0; v1.y += b1;
            }
            if (EPI == 2) {
                v0.x = fmaxf(v0.x, 0.0f); v0.y = fmaxf(v0.y, 0.0f);
                v1.x = fmaxf(v1.x, 0.0f); v1.y = fmaxf(v1.y, 0.0f);
            }
            if (EPI == 3) {
                float2 ra = *(const float2*)(resid + (size_t)r1 * Nn + cc);
                float2 rb = *(const float2*)(resid + (size_t)(r1 + 8) * Nn + cc);
                v0.x += ra.x; v0.y += ra.y; v1.x += rb.x; v1.y += rb.y;
            }
            *(float2*)(C + (size_t)r1 * Nn + cc) = v0;
            *(float2*)(C + (size_t)(r1 + 8) * Nn + cc) = v1;
        }
    }
}

// ---------------- attention: no-max softmax (scores provably small), poly exp ----------------
__global__ void attn_kernel(const float* __restrict__ qkv, float* __restrict__ out) {
    extern __shared__ float smemf[];
    float* ks = smemf;
    float* vs = smemf + PER_ * HD_;
    int bx = blockIdx.x;
    int b = bx >> 3, h = bx & 7;
    int base = b * PER_;
    int tid = threadIdx.x;

    for (int i = tid; i < PER_ * HD_; i += 256) {
        int j = i >> 5, d = i & 31;
        size_t ro = (size_t)(base + j) * (3 * CC_) + h * HD_;
        ks[i] = qkv[ro + CC_ + d];
        vs[i] = qkv[ro + 2 * CC_ + d];
    }
    __syncthreads();

    const float scale = 0.17677669529663687f; // 1/sqrt(32)
    float q[HD_];
    const float4* qp = (const float4*)(qkv + (size_t)(base + tid) * (3 * CC_) + h * HD_);
    #pragma unroll
    for (int d4 = 0; d4 < 8; d4++) {
        float4 t = qp[d4];
        q[4 * d4 + 0] = t.x * scale; q[4 * d4 + 1] = t.y * scale;
        q[4 * d4 + 2] = t.z * scale; q[4 * d4 + 3] = t.w * scale;
    }

    float den = 0.0f;
    float o[HD_];
    #pragma unroll
    for (int d = 0; d < HD_; d++) o[d] = 0.0f;

    for (int j = 0; j < PER_; j++) {
        const float* kj = ks + j * HD_;
        float s = 0.0f;
        #pragma unroll
        for (int d = 0; d < HD_; d++) s = fmaf(q[d], kj[d], s);
        float w = fast_exp(s);
        den += w;
        const float* vj = vs + j * HD_;
        #pragma unroll
        for (int d = 0; d < HD_; d++) o[d] = fmaf(w, vj[d], o[d]);
    }
    float inv = 1.0f / den;
    float* op = out + (size_t)(base + tid) * CC_ + h * HD_;
    #pragma unroll
    for (int d = 0; d < HD_; d++) op[d] = o[d] * inv;
}

// ---------------- combine: out = BN1(h1) + BN2(h2) ----------------
__global__ void combine_kernel(const float* __restrict__ g1, const float* __restrict__ b1,
                               const float* __restrict__ g2, const float* __restrict__ b2) {
    int idx = blockIdx.x * blockDim.x + threadIdx.x;
    if (idx >= NN_ * CC_) return;
    int c = idx & 255;
    const float invN = 1.0f / (float)NN_;
    float m1 = g_sum[c] * invN;
    float v1 = g_sq[c] * invN - m1 * m1;
    float s1 = g1[c] * rsqrtf(v1 + EPS_);
    float m2 = g_sum[CC_ + c] * invN;
    float v2 = g_sq[CC_ + c] * invN - m2 * m2;
    float s2 = g2[c] * rsqrtf(v2 + EPS_);
    float y1 = (g_h1[idx] - m1) * s1 + b1[c];
    float y2 = (g_h2[idx] - m2) * s2 + b2[c];
    g_out[idx] = y1 + y2;
}

// ---------------- pool: per-graph max of BN3(out3) ----------------
__global__ void pool_kernel(const float* __restrict__ g3, const float* __restrict__ b3) {
    int g = blockIdx.x;
    int c = threadIdx.x;
    const float invN = 1.0f / (float)NN_;
    float m3 = g_sum[2 * CC_ + c] * invN;
    float v3 = g_sq[2 * CC_ + c] * invN - m3 * m3;
    float s3 = g3[c] * rsqrtf(v3 + EPS_);
    float sh = b3[c] - m3 * s3;
    float mx = -INFINITY;
    for (int p = 0; p < PER_; p++) {
        float v = g_out3[(size_t)(g * PER_ + p) * CC_ + c];
        mx = fmaxf(mx, v * s3 + sh);
    }
    g_pooled[g * CC_ + c] = mx;
}

// ---------------- head: logits + log_softmax ----------------
__global__ void head_kernel(const float* __restrict__ fc_w, const float* __restrict__ fc_b,
                            float* __restrict__ out) {
    int g = blockIdx.x;
    int tid = threadIdx.x;
    __shared__ float pr[CC_];
    __shared__ float lo[NCLS_];
    __shared__ float red[2];
    pr[tid] = g_pooled[g * CC_ + tid];
    __syncthreads();
    if (tid < NCLS_) {
        float s = fc_b[tid];
        for (int c = 0; c < CC_; c++) s += pr[c] * fc_w[c * NCLS_ + tid];
        lo[tid] = s;
    }
    __syncthreads();
    if (tid == 0) {
        float mx = -INFINITY;
        for (int j = 0; j < NCLS_; j++) mx = fmaxf(mx, lo[j]);
        float se = 0.0f;
        for (int j = 0; j < NCLS_; j++) se += __expf(lo[j] - mx);
        red[0] = mx;
        red[1] = logf(se);
    }
    __syncthreads();
    if (tid < NCLS_) out[g * NCLS_ + tid] = lo[tid] - red[0] - red[1];
}

// ---------------- launch ----------------
extern "C" void kernel_launch(void* const* d_in, const int* in_sizes, int n_in,
                              void* d_out, int out_size) {
    const float* x          = (const float*)d_in[0];
    const float* W_conv     = (const float*)d_in[1];
    const float* b_conv     = (const float*)d_in[2];
    const float* bn1_g      = (const float*)d_in[3];
    const float* bn1_b      = (const float*)d_in[4];
    const float* in_proj_w  = (const float*)d_in[5];
    const float* in_proj_b  = (const float*)d_in[6];
    const float* out_proj_w = (const float*)d_in[7];
    const float* out_proj_b = (const float*)d_in[8];
    const float* bn2_g      = (const float*)d_in[9];
    const float* bn2_b      = (const float*)d_in[10];
    const float* mlp_w1     = (const float*)d_in[11];
    const float* mlp_b1     = (const float*)d_in[12];
    const float* mlp_w2     = (const float*)d_in[13];
    const float* mlp_b2     = (const float*)d_in[14];
    const float* bn3_g      = (const float*)d_in[15];
    const float* bn3_b      = (const float*)d_in[16];
    const float* fc_w       = (const float*)d_in[17];
    const float* fc_b       = (const float*)d_in[18];
    const int*   edge_index = (const int*)d_in[19];
    float* out = (float*)d_out;

    const int* row = edge_index;
    const int* col = edge_index + EE_;

    cudaFuncSetAttribute(attn_kernel, cudaFuncAttributeMaxDynamicSharedMemorySize,
                         2 * PER_ * HD_ * (int)sizeof(float));
    cudaFuncSetAttribute(gemm_mma<0>, cudaFuncAttributeMaxDynamicSharedMemorySize, GEMM_SMEM);
    cudaFuncSetAttribute(gemm_mma<1>, cudaFuncAttributeMaxDynamicSharedMemorySize, GEMM_SMEM);
    cudaFuncSetAttribute(gemm_mma<2>, cudaFuncAttributeMaxDynamicSharedMemorySize, GEMM_SMEM);
    cudaFuncSetAttribute(gemm_mma<3>, cudaFuncAttributeMaxDynamicSharedMemorySize, GEMM_SMEM);

    float* h_p;    cudaGetSymbolAddress((void**)&h_p,    g_h);
    float* h1_p;   cudaGetSymbolAddress((void**)&h1_p,   g_h1);
    float* qkv_p;  cudaGetSymbolAddress((void**)&qkv_p,  g_qkv);
    float* attn_p; cudaGetSymbolAddress((void**)&attn_p, g_attn);
    float* h2_p;   cudaGetSymbolAddress((void**)&h2_p,   g_h2);
    float* out_p;  cudaGetSymbolAddress((void**)&out_p,  g_out);
    float* ff1_p;  cudaGetSymbolAddress((void**)&ff1_p,  g_ff1);
    float* out3_p; cudaGetSymbolAddress((void**)&out3_p, g_out3);
    float* sum_p;  cudaGetSymbolAddress((void**)&sum_p,  g_sum);
    float* sq_p;   cudaGetSymbolAddress((void**)&sq_p,   g_sq);
    float* WcT_p;  cudaGetSymbolAddress((void**)&WcT_p,  g_WcT);
    float* W1T_p;  cudaGetSymbolAddress((void**)&W1T_p,  g_W1T);
    float* W2T_p;  cudaGetSymbolAddress((void**)&W2T_p,  g_W2T);

    init_kernel<<<NN_ / 256, 256>>>();
    edge_deg_kernel<<<EE_ / 256, 256>>>(col);
    dinv_kernel<<<NN_ / 256, 256>>>();

    // transpose non-transposed weights into (Nn x K) K-major for the B operand
    transpose_kernel<<<dim3(CC_ / 32, CC_ / 32), dim3(32, 8)>>>(W_conv, WcT_p, CC_, CC_);
    transpose_kernel<<<dim3(2 * CC_ / 32, CC_ / 32), dim3(32, 8)>>>(mlp_w1, W1T_p, CC_, 2 * CC_);
    transpose_kernel<<<dim3(CC_ / 32, 2 * CC_ / 32), dim3(32, 8)>>>(mlp_w2, W2T_p, 2 * CC_, CC_);

    // GCN: h = x @ W_conv (tf32 mma)
    gemm_mma<0><<<dim3(2, 256), 256, GEMM_SMEM>>>(x, WcT_p, nullptr, nullptr, h_p, CC_, CC_);
    agg_init_kernel<<<NN_ * CC_ / 256, 256>>>(x, b_conv);
    edge_agg_kernel<<<EE_ * 32 / 256, 256>>>(row, col);
    stats_kernel<<<NN_ / 128, 256>>>(h1_p, sum_p, sq_p);

    // attention branch
    gemm_mma<1><<<dim3(6, 256), 256, GEMM_SMEM>>>(x, in_proj_w, in_proj_b, nullptr, qkv_p, 3 * CC_, CC_);
    attn_kernel<<<BB_ * HH_, 256, 2 * PER_ * HD_ * (int)sizeof(float)>>>(qkv_p, attn_p);
    gemm_mma<3><<<dim3(2, 256), 256, GEMM_SMEM>>>(attn_p, out_proj_w, out_proj_b, x, h2_p, CC_, CC_);
    stats_kernel<<<NN_ / 128, 256>>>(h2_p, sum_p + CC_, sq_p + CC_);

    // combine + FFN
    combine_kernel<<<NN_ * CC_ / 256, 256>>>(bn1_g, bn1_b, bn2_g, bn2_b);
    gemm_mma<2><<<dim3(4, 256), 256, GEMM_SMEM>>>(out_p, W1T_p, mlp_b1, nullptr, ff1_p, 2 * CC_, CC_);
    gemm_mma<3><<<dim3(2, 256), 256, GEMM_SMEM>>>(ff1_p, W2T_p, mlp_b2, out_p, out3_p, CC_, 2 * CC_);
    stats_kernel<<<NN_ / 128, 256>>>(out3_p, sum_p + 2 * CC_, sq_p + 2 * CC_);

    // pool + classifier head
    pool_kernel<<<BB_, CC_>>>(bn3_g, bn3_b);
    head_kernel<<<BB_, CC_>>>(fc_w, fc_b, out);
}

// round 4
// speedup vs baseline: 2.4525x; 1.3378x over previous
#include <cuda_runtime.h>
#include <cuda_bf16.h>
#include <math.h>
#include <stdint.h>
#include <stddef.h>

// Problem constants
#define NN_ 32768
#define EE_ 524288
#define CC_ 256
#define HH_ 8
#define BB_ 128
#define NCLS_ 10
#define PER_ 256
#define HD_ 32
#define EPS_ 1e-5f

// ---------------- scratch (static device globals; no allocation) ----------------
__device__ float g_h[NN_ * CC_];        // x @ W_conv
__device__ float g_h1[NN_ * CC_];       // gcn + x (pre-BN1)
__device__ float g_qkv[NN_ * 3 * CC_];  // qkv
__device__ float g_attn[NN_ * CC_];     // attention concat output
__device__ float g_h2[NN_ * CC_];       // out_proj + x (pre-BN2)
__device__ float g_out[NN_ * CC_];      // h1 + h2 (post-BN combine)
__device__ float g_ff1[NN_ * 2 * CC_];  // relu(out@w1+b1)
__device__ float g_out3[NN_ * CC_];     // out + ff (pre-BN3)
__device__ float g_deg[NN_];
__device__ float g_dinv[NN_];
__device__ float g_sum[3 * CC_];
__device__ float g_sq[3 * CC_];
__device__ float g_pooled[BB_ * CC_];
// transposed weights (N x K, K-major) for the mma B operand
__device__ float g_WcT[CC_ * CC_];
__device__ float g_W1T[2 * CC_ * CC_];
__device__ float g_W2T[CC_ * 2 * CC_];

// ---------------- helpers ----------------
__device__ __forceinline__ uint32_t smem_u32(const void* p) {
    uint32_t a;
    asm("{ .reg .u64 t; cvta.to.shared.u64 t, %1; cvt.u32.u64 %0, t; }" : "=r"(a) : "l"(p));
    return a;
}
#define CP_COMMIT() asm volatile("cp.async.commit_group;" ::: "memory")
#define CP_WAIT1() asm volatile("cp.async.wait_group 1;" ::: "memory")
#define CP_WAIT0() asm volatile("cp.async.wait_group 0;" ::: "memory")

__device__ __forceinline__ uint32_t f2tf(float x) {
    uint32_t u;
    asm("cvt.rna.tf32.f32 %0, %1;" : "=r"(u) : "f"(x));
    return u;
}

// m16n8k8 tf32 MMA (sm_80+ PTX, assembles on plain compute_100)
__device__ __forceinline__ void mma8(float* c, const uint32_t* a, const uint32_t* b) {
    asm volatile("mma.sync.aligned.m16n8k8.row.col.f32.tf32.tf32.f32 "
        "{%0,%1,%2,%3}, {%4,%5,%6,%7}, {%8,%9}, {%0,%1,%2,%3};"
        : "+f"(c[0]), "+f"(c[1]), "+f"(c[2]), "+f"(c[3])
        : "r"(a[0]), "r"(a[1]), "r"(a[2]), "r"(a[3]), "r"(b[0]), "r"(b[1]));
}

__device__ __forceinline__ void red4(float* p, float x, float y, float z, float w) {
    asm volatile("red.global.add.v4.f32 [%0], {%1,%2,%3,%4};"
                 :: "l"(p), "f"(x), "f"(y), "f"(z), "f"(w) : "memory");
}

// fast exp on the FMA pipe (no MUFU): exp(x) = 2^(x*log2e)
__device__ __forceinline__ float fast_exp(float x) {
    float z = x * 1.4426950408889634f;
    float fz = z + 12582912.0f;                 // round-to-nearest into mantissa
    int n = __float_as_int(fz) - 0x4B400000;    // round(z)
    float f = z - (fz - 12582912.0f);           // frac in [-0.5, 0.5]
    float p = 0.0013333558f;
    p = fmaf(p, f, 0.0096181291f);
    p = fmaf(p, f, 0.0555041087f);
    p = fmaf(p, f, 0.2402265070f);
    p = fmaf(p, f, 0.6931471806f);
    p = fmaf(p, f, 1.0f);
    return p * __int_as_float((n + 127) << 23);
}

// ---------------- small kernels ----------------
__global__ void init_kernel() {
    int i = blockIdx.x * blockDim.x + threadIdx.x;
    if (i < NN_) g_deg[i] = 1.0f;
    if (i < 3 * CC_) { g_sum[i] = 0.0f; g_sq[i] = 0.0f; }
}

__global__ void edge_deg_kernel(const int* __restrict__ col) {
    int e = blockIdx.x * blockDim.x + threadIdx.x;
    if (e < EE_) atomicAdd(&g_deg[col[e]], 1.0f);
}

__global__ void dinv_kernel() {
    int i = blockIdx.x * blockDim.x + threadIdx.x;
    if (i < NN_) g_dinv[i] = rsqrtf(g_deg[i]);
}

__global__ void agg_init_kernel(const float* __restrict__ x, const float* __restrict__ b_conv) {
    int idx = blockIdx.x * blockDim.x + threadIdx.x;
    if (idx >= NN_ * CC_) return;
    int n = idx >> 8, c = idx & 255;
    float di = g_dinv[n];
    g_h1[idx] = di * di * g_h[idx] + b_conv[c] + x[idx];
}

__global__ void edge_agg_kernel(const int* __restrict__ row, const int* __restrict__ col) {
    int gt = blockIdx.x * blockDim.x + threadIdx.x;
    int e = gt >> 5;
    int lane = gt & 31;
    if (e >= EE_) return;
    int r = row[e], cl = col[e];
    float w = g_dinv[r] * g_dinv[cl];
    const float4* hp = (const float4*)(g_h + (size_t)r * CC_) + lane * 2;
    float4 a = hp[0], b = hp[1];
    float* dst = g_h1 + (size_t)cl * CC_ + lane * 8;
    red4(dst,     w * a.x, w * a.y, w * a.z, w * a.w);
    red4(dst + 4, w * b.x, w * b.y, w * b.z, w * b.w);
}

__global__ void stats_kernel(const float* __restrict__ X, float* __restrict__ sum, float* __restrict__ sq) {
    int c = threadIdx.x;
    int r0 = blockIdx.x * 128;
    float s = 0.0f, q = 0.0f;
    #pragma unroll 4
    for (int r = 0; r < 128; r++) {
        float v = X[(size_t)(r0 + r) * CC_ + c];
        s += v; q += v * v;
    }
    atomicAdd(&sum[c], s);
    atomicAdd(&sq[c], q);
}

// transpose in[R][Cc] -> out[Cc][R]
__global__ void transpose_kernel(const float* __restrict__ in, float* __restrict__ out, int R, int Cc) {
    __shared__ float t[32][33];
    int bx = blockIdx.x * 32, by = blockIdx.y * 32;
    int x = bx + threadIdx.x;
    #pragma unroll
    for (int i = 0; i < 32; i += 8) t[threadIdx.y + i][threadIdx.x] = in[(size_t)(by + threadIdx.y + i) * Cc + x];
    __syncthreads();
    int xo = by + threadIdx.x;
    #pragma unroll
    for (int i = 0; i < 32; i += 8) out[(size_t)(bx + threadIdx.y + i) * R + xo] = t[threadIdx.x][threadIdx.y + i];
}

// ---------------- tf32 mma.sync GEMM: 128x128 tile, 8 warps, cp.async double buffer ----
#define KCH 16
#define RST 20
#define CHUNK_FLOATS (128 * RST)
#define BUF_FLOATS (2 * CHUNK_FLOATS)
#define GEMM_SMEM (2 * BUF_FLOATS * 4)

__device__ __forceinline__ void ld_chunk(uint32_t dst, const float* __restrict__ g,
                                         int ld, int row0, int k0, int tid) {
    #pragma unroll
    for (int i = 0; i < 2; i++) {
        int seg = i * 256 + tid;
        int r = seg >> 2, s = seg & 3;
        uint32_t d = dst + (uint32_t)(r * (RST * 4) + s * 16);
        const float* src = g + (size_t)(row0 + r) * ld + k0 + s * 4;
        asm volatile("cp.async.cg.shared.global [%0], [%1], 16;" :: "r"(d), "l"(src));
    }
}

template<int EPI>
__global__ void __launch_bounds__(256, 2) gemm_mma(
    const float* __restrict__ A, const float* __restrict__ Bt,
    const float* __restrict__ bias, const float* __restrict__ resid,
    float* __restrict__ C, int Nn, int K)
{
    extern __shared__ float smf[];
    uint32_t sb = smem_u32(smf);
    int tid = threadIdx.x;
    int wid = tid >> 5, lane = tid & 31;
    int grp = lane >> 2, qd = lane & 3;
    int wm = wid >> 1, wn = wid & 1;
    int row0 = blockIdx.y * 128, col0 = blockIdx.x * 128;

    float acc[2][8][4];
    #pragma unroll
    for (int mf = 0; mf < 2; mf++)
        #pragma unroll
        for (int nf = 0; nf < 8; nf++)
            #pragma unroll
            for (int j = 0; j < 4; j++) acc[mf][nf][j] = 0.0f;

    int nch = K >> 4;
    ld_chunk(sb, A, K, row0, 0, tid);
    ld_chunk(sb + CHUNK_FLOATS * 4, Bt, K, col0, 0, tid);
    CP_COMMIT();

    for (int c = 0; c < nch; c++) {
        int s = c & 1;
        if (c + 1 < nch) {
            int s2 = s ^ 1;
            ld_chunk(sb + s2 * BUF_FLOATS * 4, A, K, row0, (c + 1) << 4, tid);
            ld_chunk(sb + s2 * BUF_FLOATS * 4 + CHUNK_FLOATS * 4, Bt, K, col0, (c + 1) << 4, tid);
            CP_COMMIT();
            CP_WAIT1();
        } else {
            CP_WAIT0();
        }
        __syncthreads();
        const float* As = smf + s * BUF_FLOATS;
        const float* Bs = smf + s * BUF_FLOATS + CHUNK_FLOATS;
        #pragma unroll
        for (int k8 = 0; k8 < KCH; k8 += 8) {
            uint32_t a[2][4], b[8][2];
            #pragma unroll
            for (int mf = 0; mf < 2; mf++) {
                int r = wm * 32 + mf * 16 + grp;
                a[mf][0] = f2tf(As[r * RST + k8 + qd]);
                a[mf][1] = f2tf(As[(r + 8) * RST + k8 + qd]);
                a[mf][2] = f2tf(As[r * RST + k8 + qd + 4]);
                a[mf][3] = f2tf(As[(r + 8) * RST + k8 + qd + 4]);
            }
            #pragma unroll
            for (int nf = 0; nf < 8; nf++) {
                int n = wn * 64 + nf * 8 + grp;
                b[nf][0] = f2tf(Bs[n * RST + k8 + qd]);
                b[nf][1] = f2tf(Bs[n * RST + k8 + qd + 4]);
            }
            #pragma unroll
            for (int mf = 0; mf < 2; mf++)
                #pragma unroll
                for (int nf = 0; nf < 8; nf++)
                    mma8(acc[mf][nf], a[mf], b[nf]);
        }
        __syncthreads();
    }

    #pragma unroll
    for (int mf = 0; mf < 2; mf++) {
        int r1 = row0 + wm * 32 + mf * 16 + grp;
        #pragma unroll
        for (int nf = 0; nf < 8; nf++) {
            int cc = col0 + wn * 64 + nf * 8 + qd * 2;
            float2 v0 = make_float2(acc[mf][nf][0], acc[mf][nf][1]);
            float2 v1 = make_float2(acc[mf][nf][2], acc[mf][nf][3]);
            if (EPI >= 1) {
                float b0 = bias[cc], b1 = bias[cc + 1];
                v0.x += b0; v0.y += b1; v1.x += b0; v1.y += b1;
            }
            if (EPI == 2) {
                v0.x = fmaxf(v0.x, 0.0f); v0.y = fmaxf(v0.y, 0.0f);
                v1.x = fmaxf(v1.x, 0.0f); v1.y = fmaxf(v1.y, 0.0f);
            }
            if (EPI == 3) {
                float2 ra = *(const float2*)(resid + (size_t)r1 * Nn + cc);
                float2 rb = *(const float2*)(resid + (size_t)(r1 + 8) * Nn + cc);
                v0.x += ra.x; v0.y += ra.y; v1.x += rb.x; v1.y += rb.y;
            }
            *(float2*)(C + (size_t)r1 * Nn + cc) = v0;
            *(float2*)(C + (size_t)(r1 + 8) * Nn + cc) = v1;
        }
    }
}

// ---------------- mma flash attention: one block per (graph, head) ----------------
// smem: Ks[256][36], Vs[256][36], Ps[8 warps][32][36]  (stride 36 => conflict-free)
#define AST 36
#define AT_K_OFF 0
#define AT_V_OFF (PER_ * AST)
#define AT_P_OFF (2 * PER_ * AST)
#define AT_SMEM_FLOATS (2 * PER_ * AST + 8 * 32 * AST)
#define AT_SMEM_BYTES (AT_SMEM_FLOATS * 4)

__global__ void __launch_bounds__(256) attn_mma(const float* __restrict__ qkv,
                                                float* __restrict__ out) {
    extern __shared__ float smf[];
    float* Ks = smf + AT_K_OFF;
    float* Vs = smf + AT_V_OFF;
    int tid = threadIdx.x;
    int wid = tid >> 5, lane = tid & 31;
    int grp = lane >> 2, qd = lane & 3;
    float* Ps = smf + AT_P_OFF + wid * (32 * AST);
    int bx = blockIdx.x;
    int b = bx >> 3, h = bx & 7;
    int base = b * PER_;
    int m0 = wid * 32;
    const float scale = 0.17677669529663687f; // 1/sqrt(32)

    // load K, V into smem (row-major key x dim, padded stride)
    for (int i = tid; i < PER_ * HD_; i += 256) {
        int j = i >> 5, d = i & 31;
        size_t ro = (size_t)(base + j) * (3 * CC_) + h * HD_;
        Ks[j * AST + d] = qkv[ro + CC_ + d];
        Vs[j * AST + d] = qkv[ro + 2 * CC_ + d];
    }

    // Q fragments resident in registers (scale folded in)
    uint32_t qf[2][4][4];
    #pragma unroll
    for (int mf = 0; mf < 2; mf++) {
        const float* q0 = qkv + (size_t)(base + m0 + mf * 16 + grp) * (3 * CC_) + h * HD_;
        const float* q1 = qkv + (size_t)(base + m0 + mf * 16 + grp + 8) * (3 * CC_) + h * HD_;
        #pragma unroll
        for (int kt = 0; kt < 4; kt++) {
            qf[mf][kt][0] = f2tf(q0[kt * 8 + qd] * scale);
            qf[mf][kt][1] = f2tf(q1[kt * 8 + qd] * scale);
            qf[mf][kt][2] = f2tf(q0[kt * 8 + qd + 4] * scale);
            qf[mf][kt][3] = f2tf(q1[kt * 8 + qd + 4] * scale);
        }
    }
    __syncthreads();

    float oacc[2][4][4];
    #pragma unroll
    for (int mf = 0; mf < 2; mf++)
        #pragma unroll
        for (int nf = 0; nf < 4; nf++)
            #pragma unroll
            for (int j = 0; j < 4; j++) oacc[mf][nf][j] = 0.0f;
    float den[2][2] = {{0.0f, 0.0f}, {0.0f, 0.0f}};

    for (int ct = 0; ct < 8; ct++) {
        // S = Q @ K^T for 32-key chunk
        float sacc[2][4][4];
        #pragma unroll
        for (int mf = 0; mf < 2; mf++)
            #pragma unroll
            for (int nf = 0; nf < 4; nf++)
                #pragma unroll
                for (int j = 0; j < 4; j++) sacc[mf][nf][j] = 0.0f;
        #pragma unroll
        for (int nf = 0; nf < 4; nf++) {
            int key = ct * 32 + nf * 8 + grp;
            #pragma unroll
            for (int kt = 0; kt < 4; kt++) {
                uint32_t bb[2];
                bb[0] = f2tf(Ks[key * AST + kt * 8 + qd]);
                bb[1] = f2tf(Ks[key * AST + kt * 8 + qd + 4]);
                mma8(sacc[0][nf], qf[0][kt], bb);
                mma8(sacc[1][nf], qf[1][kt], bb);
            }
        }
        // exp + den accumulate + store P tile (per-warp private region)
        __syncwarp();
        #pragma unroll
        for (int mf = 0; mf < 2; mf++) {
            #pragma unroll
            for (int nf = 0; nf < 4; nf++) {
                float w0 = fast_exp(sacc[mf][nf][0]);
                float w1 = fast_exp(sacc[mf][nf][1]);
                float w2 = fast_exp(sacc[mf][nf][2]);
                float w3 = fast_exp(sacc[mf][nf][3]);
                den[mf][0] += w0 + w1;
                den[mf][1] += w2 + w3;
                *(float2*)(Ps + (mf * 16 + grp) * AST + nf * 8 + 2 * qd) = make_float2(w0, w1);
                *(float2*)(Ps + (mf * 16 + grp + 8) * AST + nf * 8 + 2 * qd) = make_float2(w2, w3);
            }
        }
        __syncwarp();
        // O += P @ V
        #pragma unroll
        for (int kt = 0; kt < 4; kt++) {
            uint32_t pa[2][4];
            #pragma unroll
            for (int mf = 0; mf < 2; mf++) {
                pa[mf][0] = f2tf(Ps[(mf * 16 + grp) * AST + kt * 8 + qd]);
                pa[mf][1] = f2tf(Ps[(mf * 16 + grp + 8) * AST + kt * 8 + qd]);
                pa[mf][2] = f2tf(Ps[(mf * 16 + grp) * AST + kt * 8 + qd + 4]);
                pa[mf][3] = f2tf(Ps[(mf * 16 + grp + 8) * AST + kt * 8 + qd + 4]);
            }
            int k0 = ct * 32 + kt * 8;
            #pragma unroll
            for (int nf = 0; nf < 4; nf++) {
                uint32_t bb[2];
                bb[0] = f2tf(Vs[(k0 + qd) * AST + nf * 8 + grp]);
                bb[1] = f2tf(Vs[(k0 + qd + 4) * AST + nf * 8 + grp]);
                mma8(oacc[0][nf], pa[0], bb);
                mma8(oacc[1][nf], pa[1], bb);
            }
        }
    }

    // reduce den across the 4 qd lanes of each group, normalize, write out
    #pragma unroll
    for (int mf = 0; mf < 2; mf++)
        #pragma unroll
        for (int r = 0; r < 2; r++) {
            float d = den[mf][r];
            d += __shfl_xor_sync(0xFFFFFFFF, d, 1);
            d += __shfl_xor_sync(0xFFFFFFFF, d, 2);
            den[mf][r] = 1.0f / d;
        }
    #pragma unroll
    for (int mf = 0; mf < 2; mf++) {
        int r0 = base + m0 + mf * 16 + grp;
        #pragma unroll
        for (int nf = 0; nf < 4; nf++) {
            int col = h * HD_ + nf * 8 + 2 * qd;
            float2 v0 = make_float2(oacc[mf][nf][0] * den[mf][0], oacc[mf][nf][1] * den[mf][0]);
            float2 v1 = make_float2(oacc[mf][nf][2] * den[mf][1], oacc[mf][nf][3] * den[mf][1]);
            *(float2*)(out + (size_t)r0 * CC_ + col) = v0;
            *(float2*)(out + (size_t)(r0 + 8) * CC_ + col) = v1;
        }
    }
}

// ---------------- combine: out = BN1(h1) + BN2(h2) ----------------
__global__ void combine_kernel(const float* __restrict__ g1, const float* __restrict__ b1,
                               const float* __restrict__ g2, const float* __restrict__ b2) {
    int idx = blockIdx.x * blockDim.x + threadIdx.x;
    if (idx >= NN_ * CC_) return;
    int c = idx & 255;
    const float invN = 1.0f / (float)NN_;
    float m1 = g_sum[c] * invN;
    float v1 = g_sq[c] * invN - m1 * m1;
    float s1 = g1[c] * rsqrtf(v1 + EPS_);
    float m2 = g_sum[CC_ + c] * invN;
    float v2 = g_sq[CC_ + c] * invN - m2 * m2;
    float s2 = g2[c] * rsqrtf(v2 + EPS_);
    float y1 = (g_h1[idx] - m1) * s1 + b1[c];
    float y2 = (g_h2[idx] - m2) * s2 + b2[c];
    g_out[idx] = y1 + y2;
}

// ---------------- pool: per-graph max of BN3(out3) ----------------
__global__ void pool_kernel(const float* __restrict__ g3, const float* __restrict__ b3) {
    int g = blockIdx.x;
    int c = threadIdx.x;
    const float invN = 1.0f / (float)NN_;
    float m3 = g_sum[2 * CC_ + c] * invN;
    float v3 = g_sq[2 * CC_ + c] * invN - m3 * m3;
    float s3 = g3[c] * rsqrtf(v3 + EPS_);
    float sh = b3[c] - m3 * s3;
    float mx = -INFINITY;
    for (int p = 0; p < PER_; p++) {
        float v = g_out3[(size_t)(g * PER_ + p) * CC_ + c];
        mx = fmaxf(mx, v * s3 + sh);
    }
    g_pooled[g * CC_ + c] = mx;
}

// ---------------- head: logits + log_softmax ----------------
__global__ void head_kernel(const float* __restrict__ fc_w, const float* __restrict__ fc_b,
                            float* __restrict__ out) {
    int g = blockIdx.x;
    int tid = threadIdx.x;
    __shared__ float pr[CC_];
    __shared__ float lo[NCLS_];
    __shared__ float red[2];
    pr[tid] = g_pooled[g * CC_ + tid];
    __syncthreads();
    if (tid < NCLS_) {
        float s = fc_b[tid];
        for (int c = 0; c < CC_; c++) s += pr[c] * fc_w[c * NCLS_ + tid];
        lo[tid] = s;
    }
    __syncthreads();
    if (tid == 0) {
        float mx = -INFINITY;
        for (int j = 0; j < NCLS_; j++) mx = fmaxf(mx, lo[j]);
        float se = 0.0f;
        for (int j = 0; j < NCLS_; j++) se += __expf(lo[j] - mx);
        red[0] = mx;
        red[1] = logf(se);
    }
    __syncthreads();
    if (tid < NCLS_) out[g * NCLS_ + tid] = lo[tid] - red[0] - red[1];
}

// ---------------- launch ----------------
extern "C" void kernel_launch(void* const* d_in, const int* in_sizes, int n_in,
                              void* d_out, int out_size) {
    const float* x          = (const float*)d_in[0];
    const float* W_conv     = (const float*)d_in[1];
    const float* b_conv     = (const float*)d_in[2];
    const float* bn1_g      = (const float*)d_in[3];
    const float* bn1_b      = (const float*)d_in[4];
    const float* in_proj_w  = (const float*)d_in[5];
    const float* in_proj_b  = (const float*)d_in[6];
    const float* out_proj_w = (const float*)d_in[7];
    const float* out_proj_b = (const float*)d_in[8];
    const float* bn2_g      = (const float*)d_in[9];
    const float* bn2_b      = (const float*)d_in[10];
    const float* mlp_w1     = (const float*)d_in[11];
    const float* mlp_b1     = (const float*)d_in[12];
    const float* mlp_w2     = (const float*)d_in[13];
    const float* mlp_b2     = (const float*)d_in[14];
    const float* bn3_g      = (const float*)d_in[15];
    const float* bn3_b      = (const float*)d_in[16];
    const float* fc_w       = (const float*)d_in[17];
    const float* fc_b       = (const float*)d_in[18];
    const int*   edge_index = (const int*)d_in[19];
    float* out = (float*)d_out;

    const int* row = edge_index;
    const int* col = edge_index + EE_;

    cudaFuncSetAttribute(attn_mma, cudaFuncAttributeMaxDynamicSharedMemorySize, AT_SMEM_BYTES);
    cudaFuncSetAttribute(gemm_mma<0>, cudaFuncAttributeMaxDynamicSharedMemorySize, GEMM_SMEM);
    cudaFuncSetAttribute(gemm_mma<1>, cudaFuncAttributeMaxDynamicSharedMemorySize, GEMM_SMEM);
    cudaFuncSetAttribute(gemm_mma<2>, cudaFuncAttributeMaxDynamicSharedMemorySize, GEMM_SMEM);
    cudaFuncSetAttribute(gemm_mma<3>, cudaFuncAttributeMaxDynamicSharedMemorySize, GEMM_SMEM);

    float* h_p;    cudaGetSymbolAddress((void**)&h_p,    g_h);
    float* h1_p;   cudaGetSymbolAddress((void**)&h1_p,   g_h1);
    float* qkv_p;  cudaGetSymbolAddress((void**)&qkv_p,  g_qkv);
    float* attn_p; cudaGetSymbolAddress((void**)&attn_p, g_attn);
    float* h2_p;   cudaGetSymbolAddress((void**)&h2_p,   g_h2);
    float* out_p;  cudaGetSymbolAddress((void**)&out_p,  g_out);
    float* ff1_p;  cudaGetSymbolAddress((void**)&ff1_p,  g_ff1);
    float* out3_p; cudaGetSymbolAddress((void**)&out3_p, g_out3);
    float* sum_p;  cudaGetSymbolAddress((void**)&sum_p,  g_sum);
    float* sq_p;   cudaGetSymbolAddress((void**)&sq_p,   g_sq);
    float* WcT_p;  cudaGetSymbolAddress((void**)&WcT_p,  g_WcT);
    float* W1T_p;  cudaGetSymbolAddress((void**)&W1T_p,  g_W1T);
    float* W2T_p;  cudaGetSymbolAddress((void**)&W2T_p,  g_W2T);

    init_kernel<<<NN_ / 256, 256>>>();
    edge_deg_kernel<<<EE_ / 256, 256>>>(col);
    dinv_kernel<<<NN_ / 256, 256>>>();

    transpose_kernel<<<dim3(CC_ / 32, CC_ / 32), dim3(32, 8)>>>(W_conv, WcT_p, CC_, CC_);
    transpose_kernel<<<dim3(2 * CC_ / 32, CC_ / 32), dim3(32, 8)>>>(mlp_w1, W1T_p, CC_, 2 * CC_);
    transpose_kernel<<<dim3(CC_ / 32, 2 * CC_ / 32), dim3(32, 8)>>>(mlp_w2, W2T_p, 2 * CC_, CC_);

    // GCN branch
    gemm_mma<0><<<dim3(2, 256), 256, GEMM_SMEM>>>(x, WcT_p, nullptr, nullptr, h_p, CC_, CC_);
    agg_init_kernel<<<NN_ * CC_ / 256, 256>>>(x, b_conv);
    edge_agg_kernel<<<EE_ * 32 / 256, 256>>>(row, col);
    stats_kernel<<<NN_ / 128, 256>>>(h1_p, sum_p, sq_p);

    // attention branch
    gemm_mma<1><<<dim3(6, 256), 256, GEMM_SMEM>>>(x, in_proj_w, in_proj_b, nullptr, qkv_p, 3 * CC_, CC_);
    attn_mma<<<BB_ * HH_, 256, AT_SMEM_BYTES>>>(qkv_p, attn_p);
    gemm_mma<3><<<dim3(2, 256), 256, GEMM_SMEM>>>(attn_p, out_proj_w, out_proj_b, x, h2_p, CC_, CC_);
    stats_kernel<<<NN_ / 128, 256>>>(h2_p, sum_p + CC_, sq_p + CC_);

    // combine + FFN
    combine_kernel<<<NN_ * CC_ / 256, 256>>>(bn1_g, bn1_b, bn2_g, bn2_b);
    gemm_mma<2><<<dim3(4, 256), 256, GEMM_SMEM>>>(out_p, W1T_p, mlp_b1, nullptr, ff1_p, 2 * CC_, CC_);
    gemm_mma<3><<<dim3(2, 256), 256, GEMM_SMEM>>>(ff1_p, W2T_p, mlp_b2, out_p, out3_p, CC_, 2 * CC_);
    stats_kernel<<<NN_ / 128, 256>>>(out3_p, sum_p + 2 * CC_, sq_p + 2 * CC_);

    // pool + classifier head
    pool_kernel<<<BB_, CC_>>>(bn3_g, bn3_b);
    head_kernel<<<BB_, CC_>>>(fc_w, fc_b, out);
}

// round 5
// speedup vs baseline: 2.6482x; 1.0798x over previous
#include <cuda_runtime.h>
#include <cuda_bf16.h>
#include <math.h>
#include <stdint.h>
#include <stddef.h>

// Problem constants
#define NN_ 32768
#define EE_ 524288
#define CC_ 256
#define HH_ 8
#define BB_ 128
#define NCLS_ 10
#define PER_ 256
#define HD_ 32
#define EPS_ 1e-5f

// ---------------- scratch (static device globals; no allocation) ----------------
__device__ float g_h[NN_ * CC_];        // x @ W_conv
__device__ float g_h1[NN_ * CC_];       // gcn + x (pre-BN1)
__device__ float g_qkv[NN_ * 3 * CC_];  // qkv
__device__ float g_attn[NN_ * CC_];     // attention concat output
__device__ float g_h2[NN_ * CC_];       // out_proj + x (pre-BN2)
__device__ float g_out[NN_ * CC_];      // h1 + h2 (post-BN combine)
__device__ float g_ff1[NN_ * 2 * CC_];  // relu(out@w1+b1)
__device__ float g_out3[NN_ * CC_];     // out + ff (pre-BN3)
__device__ float g_dinv[NN_];
__device__ float g_sum[3 * CC_];
__device__ float g_sq[3 * CC_];
__device__ float g_pooled[BB_ * CC_];
__device__ float g_WcT[CC_ * CC_];
__device__ float g_W1T[2 * CC_ * CC_];
__device__ float g_W2T[CC_ * 2 * CC_];
// CSR for gather
__device__ int g_cnt[NN_];
__device__ int g_off[NN_ + 1];
__device__ int g_cur[NN_];
__device__ int g_src[EE_];

// ---------------- helpers ----------------
__device__ __forceinline__ uint32_t smem_u32(const void* p) {
    uint32_t a;
    asm("{ .reg .u64 t; cvta.to.shared.u64 t, %1; cvt.u32.u64 %0, t; }" : "=r"(a) : "l"(p));
    return a;
}
#define CP_COMMIT() asm volatile("cp.async.commit_group;" ::: "memory")
#define CP_WAIT1() asm volatile("cp.async.wait_group 1;" ::: "memory")
#define CP_WAIT0() asm volatile("cp.async.wait_group 0;" ::: "memory")

__device__ __forceinline__ uint32_t f2tf(float x) {
    uint32_t u;
    asm("cvt.rna.tf32.f32 %0, %1;" : "=r"(u) : "f"(x));
    return u;
}

__device__ __forceinline__ void mma8(float* c, const uint32_t* a, const uint32_t* b) {
    asm volatile("mma.sync.aligned.m16n8k8.row.col.f32.tf32.tf32.f32 "
        "{%0,%1,%2,%3}, {%4,%5,%6,%7}, {%8,%9}, {%0,%1,%2,%3};"
        : "+f"(c[0]), "+f"(c[1]), "+f"(c[2]), "+f"(c[3])
        : "r"(a[0]), "r"(a[1]), "r"(a[2]), "r"(a[3]), "r"(b[0]), "r"(b[1]));
}

// fast exp on the FMA pipe (no MUFU)
__device__ __forceinline__ float fast_exp(float x) {
    float z = x * 1.4426950408889634f;
    float fz = z + 12582912.0f;
    int n = __float_as_int(fz) - 0x4B400000;
    float f = z - (fz - 12582912.0f);
    float p = 0.0013333558f;
    p = fmaf(p, f, 0.0096181291f);
    p = fmaf(p, f, 0.0555041087f);
    p = fmaf(p, f, 0.2402265070f);
    p = fmaf(p, f, 0.6931471806f);
    p = fmaf(p, f, 1.0f);
    return p * __int_as_float((n + 127) << 23);
}

// ---------------- zero: counters + BN stats ----------------
__global__ void zero_kernel() {
    int i = blockIdx.x * blockDim.x + threadIdx.x;
    if (i < NN_) g_cnt[i] = 0;
    if (i < 3 * CC_) { g_sum[i] = 0.0f; g_sq[i] = 0.0f; }
}

// ---------------- prep: 3 weight transposes + edge histogram, one launch ----------------
__device__ __forceinline__ void transpose_tile(const float* __restrict__ in, float* __restrict__ out,
                                               int R, int Cc, int bx, int by) {
    __shared__ float t[32][33];
    int tx = threadIdx.x & 31, ty = threadIdx.x >> 5;   // 32 x 8
    int x = bx * 32 + tx;
    #pragma unroll
    for (int i = 0; i < 32; i += 8) t[ty + i][tx] = in[(size_t)(by * 32 + ty + i) * Cc + x];
    __syncthreads();
    int xo = by * 32 + tx;
    #pragma unroll
    for (int i = 0; i < 32; i += 8) out[(size_t)(bx * 32 + ty + i) * R + xo] = t[tx][ty + i];
}

__global__ void __launch_bounds__(256) prep_kernel(const float* __restrict__ W_conv,
                                                   const float* __restrict__ mlp_w1,
                                                   const float* __restrict__ mlp_w2,
                                                   const int* __restrict__ col) {
    int b = blockIdx.x;
    if (b < 64) {                       // W_conv (256x256) -> g_WcT
        transpose_tile(W_conv, g_WcT, CC_, CC_, b & 7, b >> 3);
    } else if (b < 192) {               // mlp_w1 (256x512) -> g_W1T (512x256)
        int bb = b - 64;
        transpose_tile(mlp_w1, g_W1T, CC_, 2 * CC_, bb & 15, bb >> 4);
    } else if (b < 320) {               // mlp_w2 (512x256) -> g_W2T (256x512)
        int bb = b - 192;
        transpose_tile(mlp_w2, g_W2T, 2 * CC_, CC_, bb & 7, bb >> 3);
    } else {                            // edge histogram
        int e = (b - 320) * 256 + threadIdx.x;
        if (e < EE_) atomicAdd(&g_cnt[col[e]], 1);
    }
}

// ---------------- scan: exclusive prefix sum of counts; offsets, cursors, dinv ----------------
__global__ void scan_kernel() {
    __shared__ int sp[1024];
    int t = threadIdx.x;
    int base = t * 32;
    int loc[32];
    int run = 0;
    #pragma unroll
    for (int i = 0; i < 32; i++) { loc[i] = run; run += g_cnt[base + i]; }
    sp[t] = run;
    __syncthreads();
    for (int d = 1; d < 1024; d <<= 1) {
        int v = sp[t];
        int u = (t >= d) ? sp[t - d] : 0;
        __syncthreads();
        sp[t] = v + u;
        __syncthreads();
    }
    int excl = (t > 0) ? sp[t - 1] : 0;
    #pragma unroll
    for (int i = 0; i < 32; i++) {
        int o = excl + loc[i];
        g_off[base + i] = o;
        g_cur[base + i] = o;
        g_dinv[base + i] = rsqrtf((float)(g_cnt[base + i] + 1));
    }
    if (t == 1023) g_off[NN_] = EE_;
}

// ---------------- fill CSR ----------------
__global__ void fill_kernel(const int* __restrict__ row, const int* __restrict__ col) {
    int e = blockIdx.x * blockDim.x + threadIdx.x;
    if (e >= EE_) return;
    int c = col[e];
    int p = atomicAdd(&g_cur[c], 1);
    g_src[p] = row[e];
}

// ---------------- gather: h1 = dinv[n]*sum(dinv[r]*h[r]) + dinv[n]^2*h[n] + b + x ----------------
__global__ void __launch_bounds__(256) gather_kernel(const float* __restrict__ x,
                                                     const float* __restrict__ b_conv) {
    int gw = (blockIdx.x * blockDim.x + threadIdx.x) >> 5;  // warp id = node
    int lane = threadIdx.x & 31;
    if (gw >= NN_) return;
    int beg = g_off[gw], end = g_off[gw + 1];
    float acc[8] = {0, 0, 0, 0, 0, 0, 0, 0};
    for (int e0 = beg; e0 < end; e0 += 32) {
        int nb = min(32, end - e0);
        int src = (e0 + lane < end) ? g_src[e0 + lane] : 0;
        for (int j = 0; j < nb; j++) {
            int r = __shfl_sync(0xFFFFFFFF, src, j);
            float w = g_dinv[r];
            const float4* hp = (const float4*)(g_h + (size_t)r * CC_) + lane * 2;
            float4 a = hp[0], b = hp[1];
            acc[0] = fmaf(w, a.x, acc[0]); acc[1] = fmaf(w, a.y, acc[1]);
            acc[2] = fmaf(w, a.z, acc[2]); acc[3] = fmaf(w, a.w, acc[3]);
            acc[4] = fmaf(w, b.x, acc[4]); acc[5] = fmaf(w, b.y, acc[5]);
            acc[6] = fmaf(w, b.z, acc[6]); acc[7] = fmaf(w, b.w, acc[7]);
        }
    }
    float dn = g_dinv[gw];
    float dn2 = dn * dn;
    const float4* hn = (const float4*)(g_h + (size_t)gw * CC_) + lane * 2;
    const float4* xn = (const float4*)(x + (size_t)gw * CC_) + lane * 2;
    const float4* bc = (const float4*)b_conv + lane * 2;
    float4 s0 = hn[0], s1 = hn[1];
    float4 x0 = xn[0], x1 = xn[1];
    float4 b0 = bc[0], b1 = bc[1];
    float4 o0, o1;
    o0.x = fmaf(dn, acc[0], fmaf(dn2, s0.x, b0.x + x0.x));
    o0.y = fmaf(dn, acc[1], fmaf(dn2, s0.y, b0.y + x0.y));
    o0.z = fmaf(dn, acc[2], fmaf(dn2, s0.z, b0.z + x0.z));
    o0.w = fmaf(dn, acc[3], fmaf(dn2, s0.w, b0.w + x0.w));
    o1.x = fmaf(dn, acc[4], fmaf(dn2, s1.x, b1.x + x1.x));
    o1.y = fmaf(dn, acc[5], fmaf(dn2, s1.y, b1.y + x1.y));
    o1.z = fmaf(dn, acc[6], fmaf(dn2, s1.z, b1.z + x1.z));
    o1.w = fmaf(dn, acc[7], fmaf(dn2, s1.w, b1.w + x1.w));
    float4* op = (float4*)(g_h1 + (size_t)gw * CC_) + lane * 2;
    op[0] = o0; op[1] = o1;
}

// ---------------- tf32 mma.sync GEMM: 128x128 tile, 8 warps, cp.async double buffer ----
// EPI: 2 bias+relu, 3 bias+resid, 4 split h|qkv. STATS: fused per-channel sum/sumsq.
#define KCH 16
#define RST 20
#define CHUNK_FLOATS (128 * RST)
#define BUF_FLOATS (2 * CHUNK_FLOATS)
#define GS2 (2 * BUF_FLOATS * 4 + 1024)

__device__ __forceinline__ void ld_chunk(uint32_t dst, const float* __restrict__ g,
                                         int ld, int row0, int k0, int tid) {
    #pragma unroll
    for (int i = 0; i < 2; i++) {
        int seg = i * 256 + tid;
        int r = seg >> 2, s = seg & 3;
        uint32_t d = dst + (uint32_t)(r * (RST * 4) + s * 16);
        const float* src = g + (size_t)(row0 + r) * ld + k0 + s * 4;
        asm volatile("cp.async.cg.shared.global [%0], [%1], 16;" :: "r"(d), "l"(src));
    }
}

template<int EPI, int STATS>
__global__ void __launch_bounds__(256, 2) gemm_mma(
    const float* __restrict__ A, const float* __restrict__ Bt, const float* __restrict__ Bt2,
    const float* __restrict__ bias, const float* __restrict__ resid,
    float* __restrict__ C, float* __restrict__ C2,
    float* __restrict__ gsum, float* __restrict__ gsq, int Nn, int K)
{
    extern __shared__ float smf[];
    uint32_t sb = smem_u32(smf);
    float* ssum = smf + 2 * BUF_FLOATS;        // [128]
    float* ssq  = ssum + 128;                  // [128]
    int tid = threadIdx.x;
    int wid = tid >> 5, lane = tid & 31;
    int grp = lane >> 2, qd = lane & 3;
    int wm = wid >> 1, wn = wid & 1;
    int row0 = blockIdx.y * 128, col0 = blockIdx.x * 128;

    if (STATS && tid < 256) smf[2 * BUF_FLOATS + tid] = 0.0f;

    // B operand select (EPI 4: weights concat [WcT | in_proj_w])
    const float* Bsrc = Bt;
    int bro = col0;
    if (EPI == 4 && col0 >= 256) { Bsrc = Bt2; bro = col0 - 256; }

    float acc[2][8][4];
    #pragma unroll
    for (int mf = 0; mf < 2; mf++)
        #pragma unroll
        for (int nf = 0; nf < 8; nf++)
            #pragma unroll
            for (int j = 0; j < 4; j++) acc[mf][nf][j] = 0.0f;

    int nch = K >> 4;
    ld_chunk(sb, A, K, row0, 0, tid);
    ld_chunk(sb + CHUNK_FLOATS * 4, Bsrc, K, bro, 0, tid);
    CP_COMMIT();

    for (int c = 0; c < nch; c++) {
        int s = c & 1;
        if (c + 1 < nch) {
            int s2 = s ^ 1;
            ld_chunk(sb + s2 * BUF_FLOATS * 4, A, K, row0, (c + 1) << 4, tid);
            ld_chunk(sb + s2 * BUF_FLOATS * 4 + CHUNK_FLOATS * 4, Bsrc, K, bro, (c + 1) << 4, tid);
            CP_COMMIT();
            CP_WAIT1();
        } else {
            CP_WAIT0();
        }
        __syncthreads();
        const float* As = smf + s * BUF_FLOATS;
        const float* Bs = smf + s * BUF_FLOATS + CHUNK_FLOATS;
        #pragma unroll
        for (int k8 = 0; k8 < KCH; k8 += 8) {
            uint32_t a[2][4], b[8][2];
            #pragma unroll
            for (int mf = 0; mf < 2; mf++) {
                int r = wm * 32 + mf * 16 + grp;
                a[mf][0] = f2tf(As[r * RST + k8 + qd]);
                a[mf][1] = f2tf(As[(r + 8) * RST + k8 + qd]);
                a[mf][2] = f2tf(As[r * RST + k8 + qd + 4]);
                a[mf][3] = f2tf(As[(r + 8) * RST + k8 + qd + 4]);
            }
            #pragma unroll
            for (int nf = 0; nf < 8; nf++) {
                int n = wn * 64 + nf * 8 + grp;
                b[nf][0] = f2tf(Bs[n * RST + k8 + qd]);
                b[nf][1] = f2tf(Bs[n * RST + k8 + qd + 4]);
            }
            #pragma unroll
            for (int mf = 0; mf < 2; mf++)
                #pragma unroll
                for (int nf = 0; nf < 8; nf++)
                    mma8(acc[mf][nf], a[mf], b[nf]);
        }
        __syncthreads();
    }

    // epilogue (nf outer so stats can reduce per column pair)
    #pragma unroll
    for (int nf = 0; nf < 8; nf++) {
        float sc0 = 0, sc1 = 0, qc0 = 0, qc1 = 0;
        #pragma unroll
        for (int mf = 0; mf < 2; mf++) {
            int r1 = row0 + wm * 32 + mf * 16 + grp;
            int cc = col0 + wn * 64 + nf * 8 + qd * 2;
            float2 v0 = make_float2(acc[mf][nf][0], acc[mf][nf][1]);
            float2 v1 = make_float2(acc[mf][nf][2], acc[mf][nf][3]);
            if (EPI == 2 || EPI == 3) {
                float b0 = bias[cc], b1 = bias[cc + 1];
                v0.x += b0; v0.y += b1; v1.x += b0; v1.y += b1;
            }
            if (EPI == 2) {
                v0.x = fmaxf(v0.x, 0.0f); v0.y = fmaxf(v0.y, 0.0f);
                v1.x = fmaxf(v1.x, 0.0f); v1.y = fmaxf(v1.y, 0.0f);
            }
            if (EPI == 3) {
                float2 ra = *(const float2*)(resid + (size_t)r1 * Nn + cc);
                float2 rb = *(const float2*)(resid + (size_t)(r1 + 8) * Nn + cc);
                v0.x += ra.x; v0.y += ra.y; v1.x += rb.x; v1.y += rb.y;
            }
            if (EPI == 4) {
                if (col0 < 256) {
                    *(float2*)(C + (size_t)r1 * CC_ + cc) = v0;
                    *(float2*)(C + (size_t)(r1 + 8) * CC_ + cc) = v1;
                } else {
                    int cq = cc - 256;
                    float b0 = bias[cq], b1 = bias[cq + 1];
                    v0.x += b0; v0.y += b1; v1.x += b0; v1.y += b1;
                    *(float2*)(C2 + (size_t)r1 * (3 * CC_) + cq) = v0;
                    *(float2*)(C2 + (size_t)(r1 + 8) * (3 * CC_) + cq) = v1;
                }
            } else {
                *(float2*)(C + (size_t)r1 * Nn + cc) = v0;
                *(float2*)(C + (size_t)(r1 + 8) * Nn + cc) = v1;
            }
            if (STATS) {
                sc0 += v0.x + v1.x; sc1 += v0.y + v1.y;
                qc0 += v0.x * v0.x + v1.x * v1.x;
                qc1 += v0.y * v0.y + v1.y * v1.y;
            }
        }
        if (STATS) {
            #pragma unroll
            for (int m = 4; m <= 16; m <<= 1) {
                sc0 += __shfl_xor_sync(0xFFFFFFFF, sc0, m);
                sc1 += __shfl_xor_sync(0xFFFFFFFF, sc1, m);
                qc0 += __shfl_xor_sync(0xFFFFFFFF, qc0, m);
                qc1 += __shfl_xor_sync(0xFFFFFFFF, qc1, m);
            }
            if (lane < 4) {
                int ci = wn * 64 + nf * 8 + qd * 2;
                atomicAdd(&ssum[ci], sc0); atomicAdd(&ssum[ci + 1], sc1);
                atomicAdd(&ssq[ci], qc0);  atomicAdd(&ssq[ci + 1], qc1);
            }
        }
    }
    if (STATS) {
        __syncthreads();
        if (tid < 128) {
            atomicAdd(&gsum[col0 + tid], ssum[tid]);
            atomicAdd(&gsq[col0 + tid], ssq[tid]);
        }
    }
}

// ---------------- fused attention (blocks 0..1023) + stats(h1) (blocks 1024..1279) ----------------
#define AST 36
#define AT_P_OFF (2 * PER_ * AST)
#define AT_SMEM_BYTES ((2 * PER_ * AST + 8 * 32 * AST) * 4)

__global__ void __launch_bounds__(256) attn_or_stats(const float* __restrict__ qkv,
                                                     float* __restrict__ out) {
    int tid = threadIdx.x;
    if (blockIdx.x >= 1024) {
        // stats over g_h1 -> g_sum[0..256)
        int c = tid;
        int r0 = (blockIdx.x - 1024) * 128;
        float s = 0.0f, q = 0.0f;
        #pragma unroll 4
        for (int r = 0; r < 128; r++) {
            float v = g_h1[(size_t)(r0 + r) * CC_ + c];
            s += v; q += v * v;
        }
        atomicAdd(&g_sum[c], s);
        atomicAdd(&g_sq[c], q);
        return;
    }
    extern __shared__ float smf[];
    float* Ks = smf;
    float* Vs = smf + PER_ * AST;
    int wid = tid >> 5, lane = tid & 31;
    int grp = lane >> 2, qd = lane & 3;
    float* Ps = smf + AT_P_OFF + wid * (32 * AST);
    int bx = blockIdx.x;
    int b = bx >> 3, h = bx & 7;
    int base = b * PER_;
    int m0 = wid * 32;
    const float scale = 0.17677669529663687f;

    for (int i = tid; i < PER_ * HD_; i += 256) {
        int j = i >> 5, d = i & 31;
        size_t ro = (size_t)(base + j) * (3 * CC_) + h * HD_;
        Ks[j * AST + d] = qkv[ro + CC_ + d];
        Vs[j * AST + d] = qkv[ro + 2 * CC_ + d];
    }

    uint32_t qf[2][4][4];
    #pragma unroll
    for (int mf = 0; mf < 2; mf++) {
        const float* q0 = qkv + (size_t)(base + m0 + mf * 16 + grp) * (3 * CC_) + h * HD_;
        const float* q1 = qkv + (size_t)(base + m0 + mf * 16 + grp + 8) * (3 * CC_) + h * HD_;
        #pragma unroll
        for (int kt = 0; kt < 4; kt++) {
            qf[mf][kt][0] = f2tf(q0[kt * 8 + qd] * scale);
            qf[mf][kt][1] = f2tf(q1[kt * 8 + qd] * scale);
            qf[mf][kt][2] = f2tf(q0[kt * 8 + qd + 4] * scale);
            qf[mf][kt][3] = f2tf(q1[kt * 8 + qd + 4] * scale);
        }
    }
    __syncthreads();

    float oacc[2][4][4];
    #pragma unroll
    for (int mf = 0; mf < 2; mf++)
        #pragma unroll
        for (int nf = 0; nf < 4; nf++)
            #pragma unroll
            for (int j = 0; j < 4; j++) oacc[mf][nf][j] = 0.0f;
    float den[2][2] = {{0.0f, 0.0f}, {0.0f, 0.0f}};

    for (int ct = 0; ct < 8; ct++) {
        float sacc[2][4][4];
        #pragma unroll
        for (int mf = 0; mf < 2; mf++)
            #pragma unroll
            for (int nf = 0; nf < 4; nf++)
                #pragma unroll
                for (int j = 0; j < 4; j++) sacc[mf][nf][j] = 0.0f;
        #pragma unroll
        for (int nf = 0; nf < 4; nf++) {
            int key = ct * 32 + nf * 8 + grp;
            #pragma unroll
            for (int kt = 0; kt < 4; kt++) {
                uint32_t bb[2];
                bb[0] = f2tf(Ks[key * AST + kt * 8 + qd]);
                bb[1] = f2tf(Ks[key * AST + kt * 8 + qd + 4]);
                mma8(sacc[0][nf], qf[0][kt], bb);
                mma8(sacc[1][nf], qf[1][kt], bb);
            }
        }
        __syncwarp();
        #pragma unroll
        for (int mf = 0; mf < 2; mf++) {
            #pragma unroll
            for (int nf = 0; nf < 4; nf++) {
                float w0 = fast_exp(sacc[mf][nf][0]);
                float w1 = fast_exp(sacc[mf][nf][1]);
                float w2 = fast_exp(sacc[mf][nf][2]);
                float w3 = fast_exp(sacc[mf][nf][3]);
                den[mf][0] += w0 + w1;
                den[mf][1] += w2 + w3;
                *(float2*)(Ps + (mf * 16 + grp) * AST + nf * 8 + 2 * qd) = make_float2(w0, w1);
                *(float2*)(Ps + (mf * 16 + grp + 8) * AST + nf * 8 + 2 * qd) = make_float2(w2, w3);
            }
        }
        __syncwarp();
        #pragma unroll
        for (int kt = 0; kt < 4; kt++) {
            uint32_t pa[2][4];
            #pragma unroll
            for (int mf = 0; mf < 2; mf++) {
                pa[mf][0] = f2tf(Ps[(mf * 16 + grp) * AST + kt * 8 + qd]);
                pa[mf][1] = f2tf(Ps[(mf * 16 + grp + 8) * AST + kt * 8 + qd]);
                pa[mf][2] = f2tf(Ps[(mf * 16 + grp) * AST + kt * 8 + qd + 4]);
                pa[mf][3] = f2tf(Ps[(mf * 16 + grp + 8) * AST + kt * 8 + qd + 4]);
            }
            int k0 = ct * 32 + kt * 8;
            #pragma unroll
            for (int nf = 0; nf < 4; nf++) {
                uint32_t bb[2];
                bb[0] = f2tf(Vs[(k0 + qd) * AST + nf * 8 + grp]);
                bb[1] = f2tf(Vs[(k0 + qd + 4) * AST + nf * 8 + grp]);
                mma8(oacc[0][nf], pa[0], bb);
                mma8(oacc[1][nf], pa[1], bb);
            }
        }
    }

    #pragma unroll
    for (int mf = 0; mf < 2; mf++)
        #pragma unroll
        for (int r = 0; r < 2; r++) {
            float d = den[mf][r];
            d += __shfl_xor_sync(0xFFFFFFFF, d, 1);
            d += __shfl_xor_sync(0xFFFFFFFF, d, 2);
            den[mf][r] = 1.0f / d;
        }
    #pragma unroll
    for (int mf = 0; mf < 2; mf++) {
        int r0 = base + m0 + mf * 16 + grp;
        #pragma unroll
        for (int nf = 0; nf < 4; nf++) {
            int colx = h * HD_ + nf * 8 + 2 * qd;
            float2 v0 = make_float2(oacc[mf][nf][0] * den[mf][0], oacc[mf][nf][1] * den[mf][0]);
            float2 v1 = make_float2(oacc[mf][nf][2] * den[mf][1], oacc[mf][nf][3] * den[mf][1]);
            *(float2*)(out + (size_t)r0 * CC_ + colx) = v0;
            *(float2*)(out + (size_t)(r0 + 8) * CC_ + colx) = v1;
        }
    }
}

// ---------------- combine: out = BN1(h1) + BN2(h2) ----------------
__global__ void combine_kernel(const float* __restrict__ g1, const float* __restrict__ b1,
                               const float* __restrict__ g2, const float* __restrict__ b2) {
    int idx = blockIdx.x * blockDim.x + threadIdx.x;
    if (idx >= NN_ * CC_) return;
    int c = idx & 255;
    const float invN = 1.0f / (float)NN_;
    float m1 = g_sum[c] * invN;
    float v1 = g_sq[c] * invN - m1 * m1;
    float s1 = g1[c] * rsqrtf(v1 + EPS_);
    float m2 = g_sum[CC_ + c] * invN;
    float v2 = g_sq[CC_ + c] * invN - m2 * m2;
    float s2 = g2[c] * rsqrtf(v2 + EPS_);
    float y1 = (g_h1[idx] - m1) * s1 + b1[c];
    float y2 = (g_h2[idx] - m2) * s2 + b2[c];
    g_out[idx] = y1 + y2;
}

// ---------------- pool: per-graph max of BN3(out3) ----------------
__global__ void pool_kernel(const float* __restrict__ g3, const float* __restrict__ b3) {
    int g = blockIdx.x;
    int c = threadIdx.x;
    const float invN = 1.0f / (float)NN_;
    float m3 = g_sum[2 * CC_ + c] * invN;
    float v3 = g_sq[2 * CC_ + c] * invN - m3 * m3;
    float s3 = g3[c] * rsqrtf(v3 + EPS_);
    float sh = b3[c] - m3 * s3;
    float mx = -INFINITY;
    for (int p = 0; p < PER_; p++) {
        float v = g_out3[(size_t)(g * PER_ + p) * CC_ + c];
        mx = fmaxf(mx, v * s3 + sh);
    }
    g_pooled[g * CC_ + c] = mx;
}

// ---------------- head: logits + log_softmax ----------------
__global__ void head_kernel(const float* __restrict__ fc_w, const float* __restrict__ fc_b,
                            float* __restrict__ out) {
    int g = blockIdx.x;
    int tid = threadIdx.x;
    __shared__ float pr[CC_];
    __shared__ float lo[NCLS_];
    __shared__ float red[2];
    pr[tid] = g_pooled[g * CC_ + tid];
    __syncthreads();
    if (tid < NCLS_) {
        float s = fc_b[tid];
        for (int c = 0; c < CC_; c++) s += pr[c] * fc_w[c * NCLS_ + tid];
        lo[tid] = s;
    }
    __syncthreads();
    if (tid == 0) {
        float mx = -INFINITY;
        for (int j = 0; j < NCLS_; j++) mx = fmaxf(mx, lo[j]);
        float se = 0.0f;
        for (int j = 0; j < NCLS_; j++) se += __expf(lo[j] - mx);
        red[0] = mx;
        red[1] = logf(se);
    }
    __syncthreads();
    if (tid < NCLS_) out[g * NCLS_ + tid] = lo[tid] - red[0] - red[1];
}

// ---------------- launch ----------------
extern "C" void kernel_launch(void* const* d_in, const int* in_sizes, int n_in,
                              void* d_out, int out_size) {
    const float* x          = (const float*)d_in[0];
    const float* W_conv     = (const float*)d_in[1];
    const float* b_conv     = (const float*)d_in[2];
    const float* bn1_g      = (const float*)d_in[3];
    const float* bn1_b      = (const float*)d_in[4];
    const float* in_proj_w  = (const float*)d_in[5];
    const float* in_proj_b  = (const float*)d_in[6];
    const float* out_proj_w = (const float*)d_in[7];
    const float* out_proj_b = (const float*)d_in[8];
    const float* bn2_g      = (const float*)d_in[9];
    const float* bn2_b      = (const float*)d_in[10];
    const float* mlp_w1     = (const float*)d_in[11];
    const float* mlp_b1     = (const float*)d_in[12];
    const float* mlp_w2     = (const float*)d_in[13];
    const float* mlp_b2     = (const float*)d_in[14];
    const float* bn3_g      = (const float*)d_in[15];
    const float* bn3_b      = (const float*)d_in[16];
    const float* fc_w       = (const float*)d_in[17];
    const float* fc_b       = (const float*)d_in[18];
    const int*   edge_index = (const int*)d_in[19];
    float* out = (float*)d_out;

    const int* row = edge_index;
    const int* col = edge_index + EE_;

    cudaFuncSetAttribute(attn_or_stats, cudaFuncAttributeMaxDynamicSharedMemorySize, AT_SMEM_BYTES);
    cudaFuncSetAttribute(gemm_mma<4, 0>, cudaFuncAttributeMaxDynamicSharedMemorySize, GS2);
    cudaFuncSetAttribute(gemm_mma<3, 1>, cudaFuncAttributeMaxDynamicSharedMemorySize, GS2);
    cudaFuncSetAttribute(gemm_mma<2, 0>, cudaFuncAttributeMaxDynamicSharedMemorySize, GS2);

    float* h_p;    cudaGetSymbolAddress((void**)&h_p,    g_h);
    float* qkv_p;  cudaGetSymbolAddress((void**)&qkv_p,  g_qkv);
    float* attn_p; cudaGetSymbolAddress((void**)&attn_p, g_attn);
    float* h2_p;   cudaGetSymbolAddress((void**)&h2_p,   g_h2);
    float* out_p;  cudaGetSymbolAddress((void**)&out_p,  g_out);
    float* ff1_p;  cudaGetSymbolAddress((void**)&ff1_p,  g_ff1);
    float* out3_p; cudaGetSymbolAddress((void**)&out3_p, g_out3);
    float* sum_p;  cudaGetSymbolAddress((void**)&sum_p,  g_sum);
    float* sq_p;   cudaGetSymbolAddress((void**)&sq_p,   g_sq);
    float* WcT_p;  cudaGetSymbolAddress((void**)&WcT_p,  g_WcT);
    float* W1T_p;  cudaGetSymbolAddress((void**)&W1T_p,  g_W1T);
    float* W2T_p;  cudaGetSymbolAddress((void**)&W2T_p,  g_W2T);

    // CSR build + weight prep
    zero_kernel<<<NN_ / 256, 256>>>();
    prep_kernel<<<320 + EE_ / 256, 256>>>(W_conv, mlp_w1, mlp_w2, col);
    scan_kernel<<<1, 1024>>>();
    fill_kernel<<<EE_ / 256, 256>>>(row, col);

    // fused h | qkv GEMM
    gemm_mma<4, 0><<<dim3(8, 256), 256, GS2>>>(x, WcT_p, in_proj_w, in_proj_b, nullptr,
                                               h_p, qkv_p, nullptr, nullptr, 0, CC_);
    // GCN aggregation (gather)
    gather_kernel<<<NN_ / 8, 256>>>(x, b_conv);

    // attention + stats(h1)
    attn_or_stats<<<1024 + 256, 256, AT_SMEM_BYTES>>>(qkv_p, attn_p);

    // out_proj + residual + stats(h2)
    gemm_mma<3, 1><<<dim3(2, 256), 256, GS2>>>(attn_p, out_proj_w, nullptr, out_proj_b, x,
                                               h2_p, nullptr, sum_p + CC_, sq_p + CC_, CC_, CC_);
    // combine
    combine_kernel<<<NN_ * CC_ / 256, 256>>>(bn1_g, bn1_b, bn2_g, bn2_b);
    // FFN
    gemm_mma<2, 0><<<dim3(4, 256), 256, GS2>>>(out_p, W1T_p, nullptr, mlp_b1, nullptr,
                                               ff1_p, nullptr, nullptr, nullptr, 2 * CC_, CC_);
    gemm_mma<3, 1><<<dim3(2, 256), 256, GS2>>>(ff1_p, W2T_p, nullptr, mlp_b2, out_p,
                                               out3_p, nullptr, sum_p + 2 * CC_, sq_p + 2 * CC_, CC_, 2 * CC_);
    // pool + head
    pool_kernel<<<BB_, CC_>>>(bn3_g, bn3_b);
    head_kernel<<<BB_, CC_>>>(fc_w, fc_b, out);
}